// round 1
// baseline (speedup 1.0000x reference)
#include <cuda_runtime.h>
#include <math.h>

#define NH 12
#define NB 16
#define NS 512
#define ND 768
#define NF 3072
#define NL 4
#define NDH 64
#define MROWS (NB*NS)      // 8192
#define NBH (NB*NH)        // 192

// ---------------- scratch (static device globals; no allocation) ----------------
__device__ float g_x[MROWS*ND];
__device__ float g_q[MROWS*ND];
__device__ float g_k[MROWS*ND];
__device__ float g_v[MROWS*ND];
__device__ float g_c[MROWS*ND];          // also reused as ctx output
__device__ float g_s1[(size_t)NBH*NS*NS];
__device__ float g_s2[(size_t)NBH*NS*NS]; // becomes P in place
__device__ float g_cninv[NBH*NS];
__device__ float g_tmp[MROWS*ND];
__device__ float g_h[(size_t)MROWS*NF];
__device__ float g_attn[MROWS*ND];

// ---------------- generic strided batched GEMM ----------------
// C[m,n] = sum_k A[m*rsA + k*csA] * B[k*rsB + n*csB]   (+bias, +gelu per EPI)
// batch index z -> zb = z/Hdiv, zh = z%Hdiv; per-operand offsets zb*s?b + zh*s?h
#define TM 64
#define TN 64
#define TK 16

template<int EPI>
__global__ __launch_bounds__(256) void gemm_kernel(
    const float* __restrict__ A, int rsA, int csA, long long sAb, long long sAh,
    const float* __restrict__ Bm, int rsB, int csB, long long sBb, long long sBh,
    float* __restrict__ C, int rsC, int csC, long long sCb, long long sCh,
    const float* __restrict__ bias,
    int M, int N, int K, int Hdiv)
{
    __shared__ float As[TK][68];
    __shared__ float Bs[TK][68];

    int zb = blockIdx.z / Hdiv, zh = blockIdx.z % Hdiv;
    const float* Ab = A + zb*sAb + zh*sAh;
    const float* Bb = Bm + zb*sBb + zh*sBh;
    float* Cb = C + zb*sCb + zh*sCh;

    int m0 = blockIdx.y * TM;
    int n0 = blockIdx.x * TN;
    int t  = threadIdx.x;
    int tx = t & 15, ty = t >> 4;

    float acc[4][4];
    #pragma unroll
    for (int i = 0; i < 4; i++)
        #pragma unroll
        for (int j = 0; j < 4; j++) acc[i][j] = 0.f;

    for (int k0 = 0; k0 < K; k0 += TK) {
        // ---- load A tile (A is always csA==1 in this problem) ----
        {
            int k = t % TK;
            int mb = t / TK;                // 0..15
            #pragma unroll
            for (int mm = 0; mm < 4; mm++) {
                int m = mb + mm * 16;
                As[k][m] = Ab[(long long)(m0 + m) * rsA + (long long)(k0 + k) * csA];
            }
        }
        // ---- load B tile ----
        if (csB == 1) {
            int n  = t % TN;
            int kb = t / TN;                // 0..3
            #pragma unroll
            for (int kk = 0; kk < 4; kk++) {
                int k = kb + kk * 4;
                Bs[k][n] = Bb[(long long)(k0 + k) * rsB + (n0 + n)];
            }
        } else {                            // rsB == 1 (k contiguous)
            int k  = t % TK;
            int nb = t / TK;                // 0..15
            #pragma unroll
            for (int nn = 0; nn < 4; nn++) {
                int n = nb + nn * 16;
                Bs[k][n] = Bb[(k0 + k) + (long long)(n0 + n) * csB];
            }
        }
        __syncthreads();

        #pragma unroll
        for (int k = 0; k < TK; k++) {
            float4 av = *reinterpret_cast<const float4*>(&As[k][ty * 4]);
            float4 bv = *reinterpret_cast<const float4*>(&Bs[k][tx * 4]);
            float a0[4] = {av.x, av.y, av.z, av.w};
            float b0[4] = {bv.x, bv.y, bv.z, bv.w};
            #pragma unroll
            for (int i = 0; i < 4; i++)
                #pragma unroll
                for (int j = 0; j < 4; j++)
                    acc[i][j] = fmaf(a0[i], b0[j], acc[i][j]);
        }
        __syncthreads();
    }

    #pragma unroll
    for (int i = 0; i < 4; i++) {
        int m = m0 + ty * 4 + i;
        #pragma unroll
        for (int j = 0; j < 4; j++) {
            int n = n0 + tx * 4 + j;
            float v = acc[i][j];
            if (EPI >= 1) v += bias[n];
            if (EPI == 2) v = 0.5f * v * (1.0f + erff(v * 0.70710678118654752f));
            Cb[(long long)m * rsC + (long long)n * csC] = v;
        }
    }
}

// ---------------- diag -> 1/||c|| ----------------
__global__ void diag_rsqrt_kernel(const float* __restrict__ Gc, float* __restrict__ cninv)
{
    int i = blockIdx.x * 256 + threadIdx.x;
    if (i < NBH * NS) {
        int bh = i / NS, s = i % NS;
        float d = Gc[((long long)bh * NS + s) * NS + s];
        cninv[i] = rsqrtf(d);
    }
}

// ---------------- block reduction helper ----------------
__device__ __forceinline__ float block_reduce(float v, bool ismax, float* red)
{
    int lane = threadIdx.x & 31, w = threadIdx.x >> 5;
    #pragma unroll
    for (int o = 16; o; o >>= 1) {
        float u = __shfl_xor_sync(0xffffffffu, v, o);
        v = ismax ? fmaxf(v, u) : (v + u);
    }
    if (lane == 0) red[w] = v;
    __syncthreads();
    float r = red[0];
    #pragma unroll
    for (int i = 1; i < 8; i++) r = ismax ? fmaxf(r, red[i]) : (r + red[i]);
    __syncthreads();
    return r;
}

// ---------------- blend + dual softmax; P written in place into Gqk ----------------
__global__ __launch_bounds__(256) void blend_softmax_kernel(
    const float* __restrict__ Gc, float* __restrict__ Gqk, const float* __restrict__ cninv)
{
    int l  = blockIdx.x;
    int bh = blockIdx.y;
    long long base = ((long long)bh * NS + l) * NS;
    const float* gc = Gc + base;
    float* gq = Gqk + base;
    const float* cn = cninv + bh * NS;
    int t = threadIdx.x;

    __shared__ float red[8];
    float cl = cn[l];

    float s1[2], s2[2];
    #pragma unroll
    for (int j = 0; j < 2; j++) {
        int r = t + j * 256;
        s1[j] = 1.0f - gc[r] * cl * cn[r] + (r == l ? 1.0f : 0.0f);
        s2[j] = gq[r] * 0.125f;            // 1/sqrt(64)
    }
    float m1 = block_reduce(fmaxf(s1[0], s1[1]), true, red);
    float m2 = block_reduce(fmaxf(s2[0], s2[1]), true, red);
    float e1[2], e2[2];
    #pragma unroll
    for (int j = 0; j < 2; j++) { e1[j] = expf(s1[j] - m1); e2[j] = expf(s2[j] - m2); }
    float sum1 = block_reduce(e1[0] + e1[1], false, red);
    float sum2 = block_reduce(e2[0] + e2[1], false, red);
    float inv1 = 0.5f / sum1, inv2 = 0.5f / sum2;
    #pragma unroll
    for (int j = 0; j < 2; j++) {
        int r = t + j * 256;
        gq[r] = e1[j] * inv1 + e2[j] * inv2;
    }
}

// ---------------- residual add + LayerNorm ----------------
__global__ __launch_bounds__(256) void add_ln_kernel(
    const float* __restrict__ inp, const float* __restrict__ res,
    const float* __restrict__ g, const float* __restrict__ b,
    float* __restrict__ out)
{
    long long row = blockIdx.x;
    const float* ip = inp + row * ND;
    const float* rp = res + row * ND;
    float* op = out + row * ND;
    int t = threadIdx.x;

    __shared__ float buf[ND];
    __shared__ float red[8];

    float s = 0.f;
    for (int c = t; c < ND; c += 256) {
        float v = ip[c] + rp[c];
        buf[c] = v;
        s += v;
    }
    s = block_reduce(s, false, red);
    float mu = s * (1.0f / ND);
    float vs = 0.f;
    for (int c = t; c < ND; c += 256) {
        float d = buf[c] - mu;
        vs += d * d;
    }
    vs = block_reduce(vs, false, red);
    float inv = rsqrtf(vs * (1.0f / ND) + 1e-12f);
    for (int c = t; c < ND; c += 256)
        op[c] = (buf[c] - mu) * inv * g[c] + b[c];
}

// ---------------- host ----------------
static float* sym(const void* s)
{
    void* p = nullptr;
    cudaGetSymbolAddress(&p, s);
    return (float*)p;
}

extern "C" void kernel_launch(void* const* d_in, const int* in_sizes, int n_in,
                              void* d_out, int out_size)
{
    const float* hs  = (const float*)d_in[0];
    const float* Wq  = (const float*)d_in[1];  const float* bq  = (const float*)d_in[2];
    const float* Wk  = (const float*)d_in[3];  const float* bk  = (const float*)d_in[4];
    const float* Wv  = (const float*)d_in[5];  const float* bv  = (const float*)d_in[6];
    const float* Wc  = (const float*)d_in[7];  const float* bc  = (const float*)d_in[8];
    const float* Wo  = (const float*)d_in[9];  const float* bo  = (const float*)d_in[10];
    const float* g1  = (const float*)d_in[11]; const float* b1  = (const float*)d_in[12];
    const float* Wi  = (const float*)d_in[13]; const float* bi  = (const float*)d_in[14];
    const float* Wo2 = (const float*)d_in[15]; const float* bo2 = (const float*)d_in[16];
    const float* g2  = (const float*)d_in[17]; const float* b2  = (const float*)d_in[18];

    float* X    = sym(g_x);
    float* Q    = sym(g_q);
    float* Kr   = sym(g_k);
    float* V    = sym(g_v);
    float* Cc   = sym(g_c);
    float* S1   = sym(g_s1);
    float* S2   = sym(g_s2);
    float* CN   = sym(g_cninv);
    float* TMP  = sym(g_tmp);
    float* Hbuf = sym(g_h);
    float* ATT  = sym(g_attn);

    cudaMemcpyAsync(X, hs, sizeof(float) * MROWS * ND, cudaMemcpyDeviceToDevice);

    const long long SD  = (long long)NS * ND;     // per-batch stride in row-major act
    const long long SS  = (long long)NS * NS;     // per-head score stride
    const long long HSS = (long long)NH * SS;     // per-batch score stride

    for (int i = 0; i < NL; i++) {
        const size_t wDD = (size_t)i * ND * ND;
        const size_t wDF = (size_t)i * ND * NF;

        dim3 gProj(ND / TN, MROWS / TM, 1);
        // q,k,v,c projections: [8192,768] @ [768,768] + bias, row-major out
        gemm_kernel<1><<<gProj, 256>>>(X, ND, 1, 0, 0, Wq + wDD, ND, 1, 0, 0,
                                       Q, ND, 1, 0, 0, bq + i * ND, MROWS, ND, ND, 1);
        gemm_kernel<1><<<gProj, 256>>>(X, ND, 1, 0, 0, Wk + wDD, ND, 1, 0, 0,
                                       Kr, ND, 1, 0, 0, bk + i * ND, MROWS, ND, ND, 1);
        gemm_kernel<1><<<gProj, 256>>>(X, ND, 1, 0, 0, Wv + wDD, ND, 1, 0, 0,
                                       V, ND, 1, 0, 0, bv + i * ND, MROWS, ND, ND, 1);
        gemm_kernel<1><<<gProj, 256>>>(X, ND, 1, 0, 0, Wc + wDD, ND, 1, 0, 0,
                                       Cc, ND, 1, 0, 0, bc + i * ND, MROWS, ND, ND, 1);

        // score GEMMs (batched over 192 bh): Gc = C C^T, Gqk = Q K^T
        dim3 gS(NS / TN, NS / TM, NBH);
        gemm_kernel<0><<<gS, 256>>>(Cc, ND, 1, SD, NDH,
                                    Cc, 1, ND, SD, NDH,
                                    S1, NS, 1, HSS, SS, nullptr, NS, NS, NDH, NH);
        gemm_kernel<0><<<gS, 256>>>(Q, ND, 1, SD, NDH,
                                    Kr, 1, ND, SD, NDH,
                                    S2, NS, 1, HSS, SS, nullptr, NS, NS, NDH, NH);

        // 1/||c|| from Gram diagonal
        diag_rsqrt_kernel<<<(NBH * NS + 255) / 256, 256>>>(S1, CN);

        // blend + dual softmax -> P (in place in S2)
        dim3 gB(NS, NBH);
        blend_softmax_kernel<<<gB, 256>>>(S1, S2, CN);

        // ctx = P @ V  -> row-major [B,S,D] (into Cc, free now)
        dim3 gC(NDH / TN, NS / TM, NBH);
        gemm_kernel<0><<<gC, 256>>>(S2, NS, 1, HSS, SS,
                                    V, ND, 1, SD, NDH,
                                    Cc, ND, 1, SD, NDH, nullptr, NS, NDH, NS, NH);

        // attn_out = LN(ctx @ Wo + bo + x)
        gemm_kernel<1><<<gProj, 256>>>(Cc, ND, 1, 0, 0, Wo + wDD, ND, 1, 0, 0,
                                       TMP, ND, 1, 0, 0, bo + i * ND, MROWS, ND, ND, 1);
        add_ln_kernel<<<MROWS, 256>>>(TMP, X, g1 + i * ND, b1 + i * ND, ATT);

        // h = gelu(attn @ Wi + bi)
        dim3 gWi(NF / TN, MROWS / TM, 1);
        gemm_kernel<2><<<gWi, 256>>>(ATT, ND, 1, 0, 0, Wi + wDF, NF, 1, 0, 0,
                                     Hbuf, NF, 1, 0, 0, bi + i * NF, MROWS, NF, ND, 1);

        // x = LN(h @ Wo2 + bo2 + attn)
        gemm_kernel<1><<<gProj, 256>>>(Hbuf, NF, 1, 0, 0, Wo2 + wDF, ND, 1, 0, 0,
                                       TMP, ND, 1, 0, 0, bo2 + i * ND, MROWS, ND, NF, 1);
        add_ln_kernel<<<MROWS, 256>>>(TMP, ATT, g2 + i * ND, b2 + i * ND, X);
    }

    cudaMemcpyAsync(d_out, X, sizeof(float) * MROWS * ND, cudaMemcpyDeviceToDevice);
}

// round 2
// speedup vs baseline: 1.9965x; 1.9965x over previous
#include <cuda_runtime.h>
#include <cuda_bf16.h>
#include <math.h>
#include <stdint.h>

#define NH 12
#define NB 16
#define NS 512
#define ND 768
#define NF 3072
#define NL 4
#define NDH 64
#define MROWS (NB*NS)      // 8192
#define NBH (NB*NH)        // 192

typedef __nv_bfloat16 bf16;

// ---------------- scratch ----------------
__device__ float g_xf[MROWS*ND];
__device__ float g_vf[MROWS*ND];
__device__ float g_tmp[MROWS*ND];
__device__ float g_attnf[MROWS*ND];
__device__ float g_s1[(size_t)NBH*NS*NS];
__device__ float g_s2[(size_t)NBH*NS*NS];
__device__ float g_cninv[NBH*NS];

__device__ bf16 g_xh[MROWS*ND],   g_xl[MROWS*ND];
__device__ bf16 g_qh[MROWS*ND],   g_ql[MROWS*ND];
__device__ bf16 g_kh[MROWS*ND],   g_kl[MROWS*ND];
__device__ bf16 g_ch[MROWS*ND],   g_cl[MROWS*ND];
__device__ bf16 g_ctxh[MROWS*ND], g_ctxl[MROWS*ND];
__device__ bf16 g_ath[MROWS*ND],  g_atl[MROWS*ND];
__device__ bf16 g_hh[(size_t)MROWS*NF], g_hl[(size_t)MROWS*NF];
__device__ bf16 g_ph[(size_t)NBH*NS*NS], g_pl[(size_t)NBH*NS*NS];
__device__ bf16 g_vth[NBH*NDH*NS], g_vtl[NBH*NDH*NS];

// transposed weights, bf16 hi/lo
#define WDD (768*768)
#define WDF (768*3072)
__device__ bf16 g_wqh[NL*WDD], g_wql[NL*WDD];
__device__ bf16 g_wkh[NL*WDD], g_wkl[NL*WDD];
__device__ bf16 g_wvh[NL*WDD], g_wvl[NL*WDD];
__device__ bf16 g_wch[NL*WDD], g_wcl[NL*WDD];
__device__ bf16 g_woh[NL*WDD], g_wol[NL*WDD];
__device__ bf16 g_wih[NL*WDF], g_wil[NL*WDF];
__device__ bf16 g_wo2h[NL*WDF], g_wo2l[NL*WDF];

// ---------------- helpers ----------------
__device__ __forceinline__ void split2(float v, bf16& h, bf16& l) {
    h = __float2bfloat16(v);
    l = __float2bfloat16(v - __bfloat162float(h));
}

__device__ __forceinline__ void ldsm4(uint32_t* r, uint32_t a) {
    asm volatile("ldmatrix.sync.aligned.m8n8.x4.shared.b16 {%0,%1,%2,%3}, [%4];"
        : "=r"(r[0]), "=r"(r[1]), "=r"(r[2]), "=r"(r[3]) : "r"(a));
}
__device__ __forceinline__ void ldsm2(uint32_t* r, uint32_t a) {
    asm volatile("ldmatrix.sync.aligned.m8n8.x2.shared.b16 {%0,%1}, [%2];"
        : "=r"(r[0]), "=r"(r[1]) : "r"(a));
}
__device__ __forceinline__ void mma_bf16(float* c, const uint32_t* a, const uint32_t* b) {
    asm volatile("mma.sync.aligned.m16n8k16.row.col.f32.bf16.bf16.f32 "
        "{%0,%1,%2,%3}, {%4,%5,%6,%7}, {%8,%9}, {%0,%1,%2,%3};"
        : "+f"(c[0]), "+f"(c[1]), "+f"(c[2]), "+f"(c[3])
        : "r"(a[0]), "r"(a[1]), "r"(a[2]), "r"(a[3]), "r"(b[0]), "r"(b[1]));
}
__device__ __forceinline__ void cpa16(uint32_t dst, const void* src, int sz) {
    asm volatile("cp.async.cg.shared.global [%0], [%1], 16, %2;" :: "r"(dst), "l"(src), "r"(sz));
}

// ---------------- bf16x3 NT GEMM ----------------
// C[m,n] = sum_k (Ahi+Alo)[m,k] * (Bhi+Blo)[n,k]   (3-term compensated)
// EPI: 0 f32, 1 f32+bias, 2 pair+bias, 3 pair, 4 pair+bias+gelu
#define ROWP 40        // padded K-elems per smem row (80B pitch -> conflict-free ldmatrix)
#define STAGE_B 40960  // bytes per stage (4 arrays x 5120 elems x 2B)
#define GSMEM (2*STAGE_B)

template<int EPI, bool NG>
__global__ void __launch_bounds__(256) gemm_mma(
    const bf16* __restrict__ Ah_, const bf16* __restrict__ Al_,
    int lda, long long sAb, long long sAh,
    const bf16* __restrict__ Bh_, const bf16* __restrict__ Bl_,
    int ldb, long long sBb, long long sBh,
    float* __restrict__ Cf, bf16* __restrict__ Coh, bf16* __restrict__ Col,
    int ldc, long long sCb, long long sCh,
    const float* __restrict__ bias, int N, int K, int Hdiv)
{
    extern __shared__ __align__(16) bf16 dsm[];
    const int tid = threadIdx.x, lane = tid & 31, wid = tid >> 5;
    const int wm = wid >> 2, wn = wid & 3;
    const int zb = blockIdx.z / Hdiv, zh = blockIdx.z % Hdiv;
    const int m0 = blockIdx.y * 128, n0 = blockIdx.x * 128;

    const bf16* Agh = Ah_ + zb * sAb + zh * sAh + (long long)m0 * lda;
    const bf16* Agl = Al_ + zb * sAb + zh * sAh + (long long)m0 * lda;
    const bf16* Bgh = Bh_ + zb * sBb + zh * sBh + (long long)n0 * ldb;
    const bf16* Bgl = Bl_ + zb * sBb + zh * sBh + (long long)n0 * ldb;

    uint32_t sb = (uint32_t)__cvta_generic_to_shared(dsm);

    float acc[4][4][4];
    #pragma unroll
    for (int a = 0; a < 4; a++)
        #pragma unroll
        for (int b = 0; b < 4; b++)
            #pragma unroll
            for (int c = 0; c < 4; c++) acc[a][b][c] = 0.f;

    const int KT = K >> 5;

    // issue one stage of cp.async loads
    auto issue = [&](int st, int k0) {
        #pragma unroll
        for (int i = 0; i < 2; i++) {
            int id = tid + i * 256;
            int row = id >> 2, cc = id & 3;
            uint32_t base = sb + st * STAGE_B + (uint32_t)((row * ROWP + cc * 8) * 2);
            long long go = (long long)row * lda + k0 + cc * 8;
            cpa16(base,         Agh + go, 16);
            cpa16(base + 10240, Agl + go, 16);
            int brow = row, sz = 16;
            if (NG && n0 + row >= N) { brow = 0; sz = 0; }
            long long gob = (long long)brow * ldb + k0 + cc * 8;
            cpa16(base + 20480, Bgh + gob, sz);
            cpa16(base + 30720, Bgl + gob, sz);
        }
        asm volatile("cp.async.commit_group;");
    };

    issue(0, 0);
    int st = 0;
    for (int kt = 0; kt < KT; kt++) {
        if (kt + 1 < KT) {
            issue(st ^ 1, (kt + 1) << 5);
            asm volatile("cp.async.wait_group 1;");
        } else {
            asm volatile("cp.async.wait_group 0;");
        }
        __syncthreads();

        uint32_t aB = sb + st * STAGE_B +
            (uint32_t)(((wm * 64 + (lane & 15)) * ROWP + ((lane >> 4) << 3)) * 2);
        uint32_t bB = sb + st * STAGE_B + 20480 +
            (uint32_t)(((wn * 32 + (lane & 7)) * ROWP + (((lane >> 3) & 1) << 3)) * 2);

        #pragma unroll
        for (int ks = 0; ks < 2; ks++) {
            uint32_t ah[4][4], al[4][4], bh[4][2], bl[4][2];
            #pragma unroll
            for (int mt = 0; mt < 4; mt++) {
                ldsm4(ah[mt], aB + mt * 1280 + ks * 32);
                ldsm4(al[mt], aB + 10240 + mt * 1280 + ks * 32);
            }
            #pragma unroll
            for (int nt = 0; nt < 4; nt++) {
                ldsm2(bh[nt], bB + nt * 640 + ks * 32);
                ldsm2(bl[nt], bB + 10240 + nt * 640 + ks * 32);
            }
            #pragma unroll
            for (int mt = 0; mt < 4; mt++)
                #pragma unroll
                for (int nt = 0; nt < 4; nt++) {
                    mma_bf16(acc[mt][nt], ah[mt], bh[nt]);
                    mma_bf16(acc[mt][nt], ah[mt], bl[nt]);
                    mma_bf16(acc[mt][nt], al[mt], bh[nt]);
                }
        }
        __syncthreads();
        st ^= 1;
    }

    // epilogue
    float* Cfp = Cf  ? Cf  + zb * sCb + zh * sCh : nullptr;
    bf16*  Chp = Coh ? Coh + zb * sCb + zh * sCh : nullptr;
    bf16*  Clp = Col ? Col + zb * sCb + zh * sCh : nullptr;

    #pragma unroll
    for (int mt = 0; mt < 4; mt++)
        #pragma unroll
        for (int nt = 0; nt < 4; nt++)
            #pragma unroll
            for (int h2 = 0; h2 < 2; h2++) {
                int r = m0 + wm * 64 + mt * 16 + (lane >> 2) + h2 * 8;
                int c = n0 + wn * 32 + nt * 8 + ((lane & 3) << 1);
                if (NG && c >= N) continue;
                float v0 = acc[mt][nt][h2 * 2 + 0];
                float v1 = acc[mt][nt][h2 * 2 + 1];
                if (EPI == 1 || EPI == 2 || EPI == 4) { v0 += bias[c]; v1 += bias[c + 1]; }
                if (EPI == 4) {
                    v0 = 0.5f * v0 * (1.0f + erff(v0 * 0.70710678118654752f));
                    v1 = 0.5f * v1 * (1.0f + erff(v1 * 0.70710678118654752f));
                }
                long long o = (long long)r * ldc + c;
                if (EPI <= 1) {
                    Cfp[o] = v0; Cfp[o + 1] = v1;
                } else {
                    split2(v0, Chp[o], Clp[o]);
                    split2(v1, Chp[o + 1], Clp[o + 1]);
                }
            }
}

// ---------------- fp32 -> bf16 hi/lo split (elementwise) ----------------
__global__ void conv_pair(const float4* __restrict__ src, bf16* __restrict__ h,
                          bf16* __restrict__ l, int n4)
{
    int i = blockIdx.x * 256 + threadIdx.x;
    if (i < n4) {
        float4 v = src[i];
        int b = i * 4;
        split2(v.x, h[b], l[b]);
        split2(v.y, h[b + 1], l[b + 1]);
        split2(v.z, h[b + 2], l[b + 2]);
        split2(v.w, h[b + 3], l[b + 3]);
    }
}

// ---------------- transpose + split: src fp32 [R,C] -> dst bf16 pair [C,R] ----------------
__global__ void transpose_split(const float* __restrict__ src, long long sSb, long long sSh, int Hdiv,
                                bf16* __restrict__ dh, bf16* __restrict__ dl, long long sD,
                                int R, int C, int lds, int ldd)
{
    __shared__ float t[32][33];
    int zb = blockIdx.z / Hdiv, zh = blockIdx.z % Hdiv;
    const float* s = src + zb * sSb + zh * sSh;
    bf16* oh = dh + (long long)blockIdx.z * sD;
    bf16* ol = dl + (long long)blockIdx.z * sD;
    int r0 = blockIdx.y * 32, c0 = blockIdx.x * 32;
    int tx = threadIdx.x, ty = threadIdx.y;
    #pragma unroll
    for (int i = 0; i < 4; i++) {
        int r = r0 + ty + i * 8;
        if (r < R && c0 + tx < C) t[ty + i * 8][tx] = s[(long long)r * lds + c0 + tx];
    }
    __syncthreads();
    #pragma unroll
    for (int i = 0; i < 4; i++) {
        int c = c0 + ty + i * 8, r = r0 + tx;
        if (c < C && r < R) {
            long long o = (long long)c * ldd + r;
            split2(t[tx][ty + i * 8], oh[o], ol[o]);
        }
    }
}

// ---------------- diag -> 1/||c|| ----------------
__global__ void diag_rsqrt_kernel(const float* __restrict__ Gc, float* __restrict__ cninv)
{
    int i = blockIdx.x * 256 + threadIdx.x;
    if (i < NBH * NS) {
        int bh = i / NS, s = i % NS;
        cninv[i] = rsqrtf(Gc[((long long)bh * NS + s) * NS + s]);
    }
}

// ---------------- block reduce ----------------
__device__ __forceinline__ float block_reduce(float v, bool ismax, float* red)
{
    int lane = threadIdx.x & 31, w = threadIdx.x >> 5;
    #pragma unroll
    for (int o = 16; o; o >>= 1) {
        float u = __shfl_xor_sync(0xffffffffu, v, o);
        v = ismax ? fmaxf(v, u) : (v + u);
    }
    if (lane == 0) red[w] = v;
    __syncthreads();
    float r = red[0];
    #pragma unroll
    for (int i = 1; i < 8; i++) r = ismax ? fmaxf(r, red[i]) : (r + red[i]);
    __syncthreads();
    return r;
}

// ---------------- blend + dual softmax -> P (bf16 hi/lo) ----------------
__global__ __launch_bounds__(256) void blend_softmax_kernel(
    const float* __restrict__ Gc, const float* __restrict__ Gqk,
    const float* __restrict__ cninv, bf16* __restrict__ ph, bf16* __restrict__ pl)
{
    int l = blockIdx.x;
    int bh = blockIdx.y;
    long long base = ((long long)bh * NS + l) * NS;
    const float* gc = Gc + base;
    const float* gq = Gqk + base;
    const float* cn = cninv + bh * NS;
    int t = threadIdx.x;

    __shared__ float red[8];
    float cl = cn[l];

    float s1[2], s2[2];
    #pragma unroll
    for (int j = 0; j < 2; j++) {
        int r = t + j * 256;
        s1[j] = 1.0f - gc[r] * cl * cn[r] + (r == l ? 1.0f : 0.0f);
        s2[j] = gq[r] * 0.125f;
    }
    float m1 = block_reduce(fmaxf(s1[0], s1[1]), true, red);
    float m2 = block_reduce(fmaxf(s2[0], s2[1]), true, red);
    float e1[2], e2[2];
    #pragma unroll
    for (int j = 0; j < 2; j++) { e1[j] = expf(s1[j] - m1); e2[j] = expf(s2[j] - m2); }
    float sum1 = block_reduce(e1[0] + e1[1], false, red);
    float sum2 = block_reduce(e2[0] + e2[1], false, red);
    float inv1 = 0.5f / sum1, inv2 = 0.5f / sum2;
    #pragma unroll
    for (int j = 0; j < 2; j++) {
        int r = t + j * 256;
        split2(e1[j] * inv1 + e2[j] * inv2, ph[base + r], pl[base + r]);
    }
}

// ---------------- residual add + LayerNorm (fp32 out + bf16 pair out) ----------------
__global__ __launch_bounds__(256) void add_ln_kernel(
    const float* __restrict__ inp, const float* __restrict__ res,
    const float* __restrict__ g, const float* __restrict__ b,
    float* __restrict__ outf, bf16* __restrict__ outh, bf16* __restrict__ outl)
{
    long long row = blockIdx.x;
    const float* ip = inp + row * ND;
    const float* rp = res + row * ND;
    int t = threadIdx.x;

    __shared__ float buf[ND];
    __shared__ float red[8];

    float s = 0.f;
    for (int c = t; c < ND; c += 256) {
        float v = ip[c] + rp[c];
        buf[c] = v;
        s += v;
    }
    s = block_reduce(s, false, red);
    float mu = s * (1.0f / ND);
    float vs = 0.f;
    for (int c = t; c < ND; c += 256) {
        float d = buf[c] - mu;
        vs += d * d;
    }
    vs = block_reduce(vs, false, red);
    float inv = rsqrtf(vs * (1.0f / ND) + 1e-12f);
    for (int c = t; c < ND; c += 256) {
        float v = (buf[c] - mu) * inv * g[c] + b[c];
        long long o = row * ND + c;
        outf[o] = v;
        split2(v, outh[o], outl[o]);
    }
}

// ---------------- host ----------------
static float* symf(const void* s) { void* p = nullptr; cudaGetSymbolAddress(&p, s); return (float*)p; }
static bf16*  symb(const void* s) { void* p = nullptr; cudaGetSymbolAddress(&p, s); return (bf16*)p; }

extern "C" void kernel_launch(void* const* d_in, const int* in_sizes, int n_in,
                              void* d_out, int out_size)
{
    const float* hs  = (const float*)d_in[0];
    const float* Wq  = (const float*)d_in[1];  const float* bq  = (const float*)d_in[2];
    const float* Wk  = (const float*)d_in[3];  const float* bk  = (const float*)d_in[4];
    const float* Wv  = (const float*)d_in[5];  const float* bv  = (const float*)d_in[6];
    const float* Wc  = (const float*)d_in[7];  const float* bc  = (const float*)d_in[8];
    const float* Wo  = (const float*)d_in[9];  const float* bo  = (const float*)d_in[10];
    const float* g1  = (const float*)d_in[11]; const float* b1  = (const float*)d_in[12];
    const float* Wi  = (const float*)d_in[13]; const float* bi  = (const float*)d_in[14];
    const float* Wo2 = (const float*)d_in[15]; const float* bo2 = (const float*)d_in[16];
    const float* g2  = (const float*)d_in[17]; const float* b2  = (const float*)d_in[18];

    // raise dynamic smem limit for all gemm instantiations
    cudaFuncSetAttribute(gemm_mma<0, false>, cudaFuncAttributeMaxDynamicSharedMemorySize, GSMEM);
    cudaFuncSetAttribute(gemm_mma<1, false>, cudaFuncAttributeMaxDynamicSharedMemorySize, GSMEM);
    cudaFuncSetAttribute(gemm_mma<2, false>, cudaFuncAttributeMaxDynamicSharedMemorySize, GSMEM);
    cudaFuncSetAttribute(gemm_mma<3, true>,  cudaFuncAttributeMaxDynamicSharedMemorySize, GSMEM);
    cudaFuncSetAttribute(gemm_mma<4, false>, cudaFuncAttributeMaxDynamicSharedMemorySize, GSMEM);

    float* XF   = symf(g_xf);
    float* VF   = symf(g_vf);
    float* TMP  = symf(g_tmp);
    float* ATTF = symf(g_attnf);
    float* S1   = symf(g_s1);
    float* S2   = symf(g_s2);
    float* CN   = symf(g_cninv);

    bf16 *XH = symb(g_xh), *XL = symb(g_xl);
    bf16 *QH = symb(g_qh), *QL = symb(g_ql);
    bf16 *KH = symb(g_kh), *KL = symb(g_kl);
    bf16 *CH = symb(g_ch), *CL = symb(g_cl);
    bf16 *CXH = symb(g_ctxh), *CXL = symb(g_ctxl);
    bf16 *ATH = symb(g_ath), *ATL = symb(g_atl);
    bf16 *HH = symb(g_hh), *HL = symb(g_hl);
    bf16 *PH = symb(g_ph), *PL = symb(g_pl);
    bf16 *VTH = symb(g_vth), *VTL = symb(g_vtl);

    bf16 *WQH = symb(g_wqh), *WQL = symb(g_wql);
    bf16 *WKH = symb(g_wkh), *WKL = symb(g_wkl);
    bf16 *WVH = symb(g_wvh), *WVL = symb(g_wvl);
    bf16 *WCH = symb(g_wch), *WCL = symb(g_wcl);
    bf16 *WOH = symb(g_woh), *WOL = symb(g_wol);
    bf16 *WIH = symb(g_wih), *WIL = symb(g_wil);
    bf16 *WO2H = symb(g_wo2h), *WO2L = symb(g_wo2l);

    const long long SD  = (long long)NS * ND;      // 512*768
    const long long SS  = (long long)NS * NS;      // 512*512
    const long long HSS = (long long)NH * SS;
    const long long VTS = (long long)NDH * NS;     // 64*512

    dim3 tb(32, 8);
    // weight transposes (all 4 layers batched over z)
    transpose_split<<<dim3(24, 24, NL), tb>>>(Wq,  WDD, 0, 1, WQH,  WQL,  WDD, 768, 768, 768, 768);
    transpose_split<<<dim3(24, 24, NL), tb>>>(Wk,  WDD, 0, 1, WKH,  WKL,  WDD, 768, 768, 768, 768);
    transpose_split<<<dim3(24, 24, NL), tb>>>(Wv,  WDD, 0, 1, WVH,  WVL,  WDD, 768, 768, 768, 768);
    transpose_split<<<dim3(24, 24, NL), tb>>>(Wc,  WDD, 0, 1, WCH,  WCL,  WDD, 768, 768, 768, 768);
    transpose_split<<<dim3(24, 24, NL), tb>>>(Wo,  WDD, 0, 1, WOH,  WOL,  WDD, 768, 768, 768, 768);
    transpose_split<<<dim3(96, 24, NL), tb>>>(Wi,  WDF, 0, 1, WIH,  WIL,  WDF, 768, 3072, 3072, 768);
    transpose_split<<<dim3(24, 96, NL), tb>>>(Wo2, WDF, 0, 1, WO2H, WO2L, WDF, 3072, 768, 768, 3072);

    cudaMemcpyAsync(XF, hs, sizeof(float) * MROWS * ND, cudaMemcpyDeviceToDevice);
    conv_pair<<<(MROWS * ND / 4 + 255) / 256, 256>>>((const float4*)hs, XH, XL, MROWS * ND / 4);

    for (int i = 0; i < NL; i++) {
        const size_t oDD = (size_t)i * WDD, oDF = (size_t)i * WDF;

        dim3 gP(6, 64, 1);
        // Q,K,C projections -> bf16 pair; V -> fp32
        gemm_mma<2, false><<<gP, 256, GSMEM>>>(XH, XL, 768, 0, 0, WQH + oDD, WQL + oDD, 768, 0, 0,
            nullptr, QH, QL, 768, 0, 0, bq + i * ND, 768, 768, 1);
        gemm_mma<2, false><<<gP, 256, GSMEM>>>(XH, XL, 768, 0, 0, WKH + oDD, WKL + oDD, 768, 0, 0,
            nullptr, KH, KL, 768, 0, 0, bk + i * ND, 768, 768, 1);
        gemm_mma<2, false><<<gP, 256, GSMEM>>>(XH, XL, 768, 0, 0, WCH + oDD, WCL + oDD, 768, 0, 0,
            nullptr, CH, CL, 768, 0, 0, bc + i * ND, 768, 768, 1);
        gemm_mma<1, false><<<gP, 256, GSMEM>>>(XH, XL, 768, 0, 0, WVH + oDD, WVL + oDD, 768, 0, 0,
            VF, nullptr, nullptr, 768, 0, 0, bv + i * ND, 768, 768, 1);

        // V -> VT bf16 pair, per head
        transpose_split<<<dim3(2, 16, NBH), tb>>>(VF, SD, NDH, NH, VTH, VTL, VTS, 512, 64, 768, 512);

        // score gram GEMMs (batched over bh)
        dim3 gS(4, 4, NBH);
        gemm_mma<0, false><<<gS, 256, GSMEM>>>(CH, CL, 768, SD, NDH, CH, CL, 768, SD, NDH,
            S1, nullptr, nullptr, 512, HSS, SS, nullptr, 512, 64, NH);
        gemm_mma<0, false><<<gS, 256, GSMEM>>>(QH, QL, 768, SD, NDH, KH, KL, 768, SD, NDH,
            S2, nullptr, nullptr, 512, HSS, SS, nullptr, 512, 64, NH);

        diag_rsqrt_kernel<<<(NBH * NS + 255) / 256, 256>>>(S1, CN);
        blend_softmax_kernel<<<dim3(NS, NBH), 256>>>(S1, S2, CN, PH, PL);

        // ctx = P @ V^T  (N=64, guarded)
        dim3 gC(1, 4, NBH);
        gemm_mma<3, true><<<gC, 256, GSMEM>>>(PH, PL, 512, HSS, SS, VTH, VTL, 512, (long long)NH * VTS, VTS,
            nullptr, CXH, CXL, 768, SD, NDH, nullptr, 64, 512, NH);

        // attn_out = LN(ctx @ Wo + bo + x)
        gemm_mma<1, false><<<gP, 256, GSMEM>>>(CXH, CXL, 768, 0, 0, WOH + oDD, WOL + oDD, 768, 0, 0,
            TMP, nullptr, nullptr, 768, 0, 0, bo + i * ND, 768, 768, 1);
        add_ln_kernel<<<MROWS, 256>>>(TMP, XF, g1 + i * ND, b1 + i * ND, ATTF, ATH, ATL);

        // h = gelu(attn @ Wi + bi) -> bf16 pair
        dim3 gI(24, 64, 1);
        gemm_mma<4, false><<<gI, 256, GSMEM>>>(ATH, ATL, 768, 0, 0, WIH + oDF, WIL + oDF, 768, 0, 0,
            nullptr, HH, HL, 3072, 0, 0, bi + i * NF, 3072, 768, 1);

        // x = LN(h @ Wo2 + bo2 + attn)
        gemm_mma<1, false><<<gP, 256, GSMEM>>>(HH, HL, 3072, 0, 0, WO2H + oDF, WO2L + oDF, 3072, 0, 0,
            TMP, nullptr, nullptr, 768, 0, 0, bo2 + i * ND, 768, 3072, 1);
        add_ln_kernel<<<MROWS, 256>>>(TMP, ATTF, g2 + i * ND, b2 + i * ND, XF, XH, XL);
    }

    cudaMemcpyAsync(d_out, XF, sizeof(float) * MROWS * ND, cudaMemcpyDeviceToDevice);
}

// round 4
// speedup vs baseline: 4.3761x; 2.1919x over previous
#include <cuda_runtime.h>
#include <cuda_bf16.h>
#include <math.h>
#include <stdint.h>

#define NH 12
#define NB 16
#define NS 512
#define ND 768
#define NF 3072
#define NL 4
#define NDH 64
#define MROWS (NB*NS)      // 8192
#define NBH (NB*NH)        // 192

typedef __nv_bfloat16 bf16;

#if defined(__CUDA_ARCH_FEAT_SM103_ALL)
#define HAS_TC 1
#else
#define HAS_TC 0
#endif

// ---------------- scratch ----------------
__device__ float g_xf[MROWS*ND];
__device__ float g_vf[MROWS*ND];
__device__ float g_tmp[MROWS*ND];
__device__ float g_attnf[MROWS*ND];
__device__ float g_s1[(size_t)NBH*NS*NS];
__device__ float g_s2[(size_t)NBH*NS*NS];
__device__ float g_cninv[NBH*NS];

__device__ bf16 g_xh[MROWS*ND],   g_xl[MROWS*ND];
__device__ bf16 g_qh[MROWS*ND],   g_ql[MROWS*ND];
__device__ bf16 g_kh[MROWS*ND],   g_kl[MROWS*ND];
__device__ bf16 g_ch[MROWS*ND],   g_cl[MROWS*ND];
__device__ bf16 g_ctxh[MROWS*ND], g_ctxl[MROWS*ND];
__device__ bf16 g_ath[MROWS*ND],  g_atl[MROWS*ND];
__device__ bf16 g_hh[(size_t)MROWS*NF], g_hl[(size_t)MROWS*NF];
__device__ bf16 g_ph[(size_t)NBH*NS*NS], g_pl[(size_t)NBH*NS*NS];
__device__ bf16 g_vth[NBH*NDH*NS], g_vtl[NBH*NDH*NS];

#define WDD (768*768)
#define WDF (768*3072)
__device__ bf16 g_wqh[NL*WDD], g_wql[NL*WDD];
__device__ bf16 g_wkh[NL*WDD], g_wkl[NL*WDD];
__device__ bf16 g_wvh[NL*WDD], g_wvl[NL*WDD];
__device__ bf16 g_wch[NL*WDD], g_wcl[NL*WDD];
__device__ bf16 g_woh[NL*WDD], g_wol[NL*WDD];
__device__ bf16 g_wih[NL*WDF], g_wil[NL*WDF];
__device__ bf16 g_wo2h[NL*WDF], g_wo2l[NL*WDF];

// ---------------- helpers ----------------
__device__ __forceinline__ void split2(float v, bf16& h, bf16& l) {
    h = __float2bfloat16(v);
    l = __float2bfloat16(v - __bfloat162float(h));
}

__device__ __forceinline__ void cpa16(uint32_t dst, const void* src, int sz) {
    asm volatile("cp.async.cg.shared.global [%0], [%1], 16, %2;" :: "r"(dst), "l"(src), "r"(sz));
}

#define FENCE_PROXY_ASYNC() \
    asm volatile("fence.proxy.async.shared::cta;" ::: "memory")

#if HAS_TC
// -------- tcgen05 machinery (sm_103a pass only) --------
__device__ __forceinline__ uint32_t elect_one_pred() {
    uint32_t pred;
    asm volatile(
        "{\n\t.reg .pred p;\n\t"
        "elect.sync _|p, 0xFFFFFFFF;\n\t"
        "selp.b32 %0, 1, 0, p;\n\t}"
        : "=r"(pred));
    return pred;
}

static constexpr uint64_t SMEM_DESC_BASE_SW128 =
    (uint64_t(2) << 61) | (uint64_t(1) << 46) | (uint64_t(64) << 32) | (uint64_t(1) << 16);
#define MAKE_SMEM_DESC(base_addr) \
    (SMEM_DESC_BASE_SW128 | ((uint64_t)((base_addr) >> 4) & 0x3FFF))

#define TCGEN05_ALLOC(smem_result_addr, nCols) \
    asm volatile("tcgen05.alloc.cta_group::1.sync.aligned.shared::cta.b32 [%0], %1;" \
        :: "r"((uint32_t)(smem_result_addr)), "r"((uint32_t)(nCols)) : "memory")
#define TCGEN05_DEALLOC(tmem_addr, nCols) \
    asm volatile("tcgen05.dealloc.cta_group::1.sync.aligned.b32 %0, %1;" \
        :: "r"(tmem_addr), "r"((uint32_t)(nCols)))
#define TCGEN05_RELINQ() \
    asm volatile("tcgen05.relinquish_alloc_permit.cta_group::1.sync.aligned;")
#define TCGEN05_COMMIT(mbar) \
    asm volatile("tcgen05.commit.cta_group::1.mbarrier::arrive::one.shared::cluster.b64 [%0];" \
        :: "r"((uint32_t)(mbar)) : "memory")
#define TCGEN05_WAIT_LD() \
    asm volatile("tcgen05.wait::ld.sync.aligned;" ::: "memory")
#define TCGEN05_FENCE_AFTER() \
    asm volatile("tcgen05.fence::after_thread_sync;" ::: "memory")
#define TCGEN05_FENCE_BEFORE() \
    asm volatile("tcgen05.fence::before_thread_sync;" ::: "memory")

#define MBARRIER_INIT(mbar, count) \
    asm volatile("mbarrier.init.shared.b64 [%0], %1;" \
        :: "r"((uint32_t)(mbar)), "r"((uint32_t)(count)) : "memory")
#define MBARRIER_INVAL(mbar) \
    asm volatile("mbarrier.inval.shared.b64 [%0];" :: "r"((uint32_t)(mbar)) : "memory")
#define MBARRIER_WAIT_PARITY(mbar_addr, phase_parity) do { \
    uint32_t _mbar = (uint32_t)(mbar_addr); \
    uint32_t _parity = (uint32_t)(phase_parity); \
    uint32_t _done; \
    asm volatile( \
        "{\n\t.reg .pred p;\n\t" \
        "mbarrier.try_wait.parity.acquire.cta.shared::cta.b64 p, [%1], %2;\n\t" \
        "selp.b32 %0, 1, 0, p;\n\t}" \
        : "=r"(_done) : "r"(_mbar), "r"(_parity) : "memory"); \
    if (!_done) { \
        asm volatile( \
            "{\n\t.reg .pred P1;\n\t" \
            "WAIT_LOOP_%=:\n\t" \
            "mbarrier.try_wait.parity.acquire.cta.shared::cta.b64 P1, [%0], %1, 0x989680;\n\t" \
            "@P1 bra.uni WAIT_DONE_%=;\n\t" \
            "bra.uni WAIT_LOOP_%=;\n\t" \
            "WAIT_DONE_%=:\n\t}" \
            :: "r"(_mbar), "r"(_parity) : "memory"); \
    } \
} while(0)

#define TCGEN05_LD_32X32B_X32(r, tmem_addr) \
    asm volatile( \
        "tcgen05.ld.sync.aligned.32x32b.x32.b32 " \
        "{%0, %1, %2, %3, %4, %5, %6, %7, " \
        " %8, %9, %10, %11, %12, %13, %14, %15, " \
        " %16, %17, %18, %19, %20, %21, %22, %23, " \
        " %24, %25, %26, %27, %28, %29, %30, %31}, [%32];" \
        : "=r"((r)[0]),  "=r"((r)[1]),  "=r"((r)[2]),  "=r"((r)[3]), \
          "=r"((r)[4]),  "=r"((r)[5]),  "=r"((r)[6]),  "=r"((r)[7]), \
          "=r"((r)[8]),  "=r"((r)[9]),  "=r"((r)[10]), "=r"((r)[11]), \
          "=r"((r)[12]), "=r"((r)[13]), "=r"((r)[14]), "=r"((r)[15]), \
          "=r"((r)[16]), "=r"((r)[17]), "=r"((r)[18]), "=r"((r)[19]), \
          "=r"((r)[20]), "=r"((r)[21]), "=r"((r)[22]), "=r"((r)[23]), \
          "=r"((r)[24]), "=r"((r)[25]), "=r"((r)[26]), "=r"((r)[27]), \
          "=r"((r)[28]), "=r"((r)[29]), "=r"((r)[30]), "=r"((r)[31]) \
        : "r"(tmem_addr))

__device__ __forceinline__ void mma_f16_ss(uint32_t d, uint64_t ad, uint64_t bd,
                                           uint32_t idesc, uint32_t en) {
    asm volatile(
        "{\n\t.reg .pred p;\n\t"
        "setp.ne.u32 p, %5, 0;\n\t"
        "tcgen05.mma.cta_group::1.kind::f16 [%0], %1, %2, %3, {%4, %4, %4, %4}, p;\n\t}"
        :: "r"(d), "l"(ad), "l"(bd), "r"(idesc), "r"(0u), "r"(en) : "memory");
}
#else
// -------- legacy mma.sync machinery (base sm_103 pass) --------
__device__ __forceinline__ void ldsm4(uint32_t* r, uint32_t a) {
    asm volatile("ldmatrix.sync.aligned.m8n8.x4.shared.b16 {%0,%1,%2,%3}, [%4];"
        : "=r"(r[0]), "=r"(r[1]), "=r"(r[2]), "=r"(r[3]) : "r"(a));
}
__device__ __forceinline__ void ldsm2(uint32_t* r, uint32_t a) {
    asm volatile("ldmatrix.sync.aligned.m8n8.x2.shared.b16 {%0,%1}, [%2];"
        : "=r"(r[0]), "=r"(r[1]) : "r"(a));
}
__device__ __forceinline__ void mma_bf16(float* c, const uint32_t* a, const uint32_t* b) {
    asm volatile("mma.sync.aligned.m16n8k16.row.col.f32.bf16.bf16.f32 "
        "{%0,%1,%2,%3}, {%4,%5,%6,%7}, {%8,%9}, {%0,%1,%2,%3};"
        : "+f"(c[0]), "+f"(c[1]), "+f"(c[2]), "+f"(c[3])
        : "r"(a[0]), "r"(a[1]), "r"(a[2]), "r"(a[3]), "r"(b[0]), "r"(b[1]));
}
#endif

// ---------------- dual-engine bf16x3 NT GEMM ----------------
// C[m,n] = sum_k (Ahi+Alo)[m,k]*(Bhi+Blo)[n,k]  (3-term compensated)
// 128x128 tile, K chunks of 64, double buffered, SW128 smem layout.
// EPI: 0 f32, 1 f32+bias, 2 pair+bias, 3 pair, 4 pair+bias+gelu
#define TILE_B 16384
#define STAGE_BYTES (4*TILE_B)    // 65536
#define CTRL (2*STAGE_BYTES)      // 131072
#define GSM (CTRL + 64)

template<int EPI>
__global__ void __launch_bounds__(256) gemm_tc(
    const bf16* __restrict__ Ah_, const bf16* __restrict__ Al_,
    int lda, long long sAb, long long sAh,
    const bf16* __restrict__ Bh_, const bf16* __restrict__ Bl_,
    int ldb, long long sBb, long long sBh,
    float* __restrict__ Cf, bf16* __restrict__ Coh, bf16* __restrict__ Col,
    int ldc, long long sCb, long long sCh,
    const float* __restrict__ bias,
    int N, int K, int Hdiv, uint32_t idesc)
{
    extern __shared__ __align__(1024) char dsm[];
    const int tid = threadIdx.x, lane = tid & 31, wid = tid >> 5;
    const int zb = blockIdx.z / Hdiv, zh = blockIdx.z % Hdiv;
    const int m0 = blockIdx.y * 128, n0 = blockIdx.x * 128;
    const int nB = min(128, N - n0);     // valid B rows / output cols

    uint32_t sb = (uint32_t)__cvta_generic_to_shared(dsm);

#if HAS_TC
    uint32_t ctl = sb + CTRL;
    uint32_t mb0 = ctl + 8, mb1 = ctl + 16;
    if (tid == 0) { MBARRIER_INIT(mb0, 1); MBARRIER_INIT(mb1, 1); }
    if (wid == 4) { TCGEN05_ALLOC(ctl, 128); TCGEN05_RELINQ(); }
    __syncthreads();
    uint32_t tmem;
    asm volatile("ld.shared.b32 %0, [%1];" : "=r"(tmem) : "r"(ctl));
    int ph0 = 0, ph1 = 0;
#else
    const int wm = wid >> 2, wn = wid & 3;
    float acc[4][4][4];
    #pragma unroll
    for (int a = 0; a < 4; a++)
        #pragma unroll
        for (int b = 0; b < 4; b++)
            #pragma unroll
            for (int c = 0; c < 4; c++) acc[a][b][c] = 0.f;
#endif

    const bf16* Agh = Ah_ + zb*sAb + zh*sAh + (long long)m0 * lda;
    const bf16* Agl = Al_ + zb*sAb + zh*sAh + (long long)m0 * lda;
    const bf16* Bgh = Bh_ + zb*sBb + zh*sBh + (long long)n0 * ldb;
    const bf16* Bgl = Bl_ + zb*sBb + zh*sBh + (long long)n0 * ldb;

    const int KT = K >> 6;

    // load one 4-tile stage (SW128 swizzled) and commit the group
    auto issue = [&](int buf, int k0) {
        const uint32_t sbase = sb + buf * STAGE_BYTES;
        #pragma unroll
        for (int i = 0; i < 4; i++) {
            int t = tid + (i << 8);
            int row = t >> 3, cc = t & 7;
            uint32_t off = (uint32_t)((row << 7) + (cc << 4));
            uint32_t sw = off ^ ((off >> 3) & 0x70);
            long long ga = (long long)row * lda + k0 + (cc << 3);
            cpa16(sbase + sw,              Agh + ga, 16);
            cpa16(sbase + TILE_B + sw,     Agl + ga, 16);
            int bs = 16, br = row;
            if (row >= nB) { bs = 0; br = 0; }
            long long gb = (long long)br * ldb + k0 + (cc << 3);
            cpa16(sbase + 2*TILE_B + sw,   Bgh + gb, bs);
            cpa16(sbase + 3*TILE_B + sw,   Bgl + gb, bs);
        }
        asm volatile("cp.async.commit_group;");
    };

    issue(0, 0);
    for (int kt = 0; kt < KT; kt++) {
        const int buf = kt & 1;
        if (kt + 1 < KT) {
#if HAS_TC
            // buffer buf^1 was consumed by MMA of stage kt-1: gate on its commit
            if (kt >= 1) {
                if ((buf ^ 1) == 0) { MBARRIER_WAIT_PARITY(mb0, ph0); ph0 ^= 1; }
                else                { MBARRIER_WAIT_PARITY(mb1, ph1); ph1 ^= 1; }
            }
#endif
            issue(buf ^ 1, (kt + 1) << 6);
            asm volatile("cp.async.wait_group 1;");
        } else {
            asm volatile("cp.async.wait_group 0;");
        }
        FENCE_PROXY_ASYNC();
        __syncthreads();

        const uint32_t sbase = sb + buf * STAGE_BYTES;
#if HAS_TC
        if (wid == 4) {
            if (elect_one_pred()) {
                uint64_t dah = MAKE_SMEM_DESC(sbase);
                uint64_t dal = MAKE_SMEM_DESC(sbase + TILE_B);
                uint64_t dbh = MAKE_SMEM_DESC(sbase + 2*TILE_B);
                uint64_t dbl = MAKE_SMEM_DESC(sbase + 3*TILE_B);
                #pragma unroll
                for (int s = 0; s < 4; s++) {
                    uint32_t en0 = (kt == 0 && s == 0) ? 0u : 1u;
                    mma_f16_ss(tmem, dah + s*2, dbh + s*2, idesc, en0);
                    mma_f16_ss(tmem, dah + s*2, dbl + s*2, idesc, 1u);
                    mma_f16_ss(tmem, dal + s*2, dbh + s*2, idesc, 1u);
                }
                TCGEN05_COMMIT(buf ? mb1 : mb0);
            }
        }
#else
        {
            const uint32_t swzA = (uint32_t)(lane & 7) << 4;
            const uint32_t rowA = (uint32_t)(wm * 64 + (lane & 15));
            const uint32_t halfA = (uint32_t)((lane >> 4) << 4);
            const uint32_t rowB = (uint32_t)(wn * 32 + (lane & 7));
            const uint32_t halfB = (uint32_t)(((lane >> 3) & 1) << 4);
            #pragma unroll
            for (int ks = 0; ks < 4; ks++) {
                uint32_t kbA = ((uint32_t)(ks * 32) + halfA) ^ swzA;
                uint32_t kbB = ((uint32_t)(ks * 32) + halfB) ^ swzA;
                uint32_t ah[4][4], al[4][4], bh[4][2], bl[4][2];
                #pragma unroll
                for (int mt = 0; mt < 4; mt++) {
                    uint32_t ad = sbase + ((rowA + mt * 16) << 7) + kbA;
                    ldsm4(ah[mt], ad);
                    ldsm4(al[mt], ad + TILE_B);
                }
                #pragma unroll
                for (int nt = 0; nt < 4; nt++) {
                    uint32_t bd = sbase + 2*TILE_B + ((rowB + nt * 8) << 7) + kbB;
                    ldsm2(bh[nt], bd);
                    ldsm2(bl[nt], bd + TILE_B);
                }
                #pragma unroll
                for (int mt = 0; mt < 4; mt++)
                    #pragma unroll
                    for (int nt = 0; nt < 4; nt++) {
                        mma_bf16(acc[mt][nt], ah[mt], bh[nt]);
                        mma_bf16(acc[mt][nt], ah[mt], bl[nt]);
                        mma_bf16(acc[mt][nt], al[mt], bh[nt]);
                    }
            }
        }
#endif
        __syncthreads();
    }

    float* Cfp = Cf  ? Cf  + zb*sCb + zh*sCh : nullptr;
    bf16*  Chp = Coh ? Coh + zb*sCb + zh*sCh : nullptr;
    bf16*  Clp = Col ? Col + zb*sCb + zh*sCh : nullptr;

#if HAS_TC
    // final MMA completion (commit tracks all prior mma)
    if (((KT - 1) & 1) == 0) { MBARRIER_WAIT_PARITY(mb0, ph0); }
    else                     { MBARRIER_WAIT_PARITY(mb1, ph1); }
    TCGEN05_FENCE_AFTER();

    float* stg = (float*)dsm;
    for (int cb = 0; cb < nB; cb += 32) {
        if (wid < 4) {
            uint32_t d[32];
            TCGEN05_LD_32X32B_X32(d, tmem + cb);
            TCGEN05_WAIT_LD();
            int row = (wid << 5) + lane;
            #pragma unroll
            for (int j = 0; j < 32; j++) stg[row * 33 + j] = __uint_as_float(d[j]);
        }
        __syncthreads();
        #pragma unroll
        for (int it = 0; it < 4; it++) {
            int row = (it << 5) + (tid >> 3);
            int cc = (tid & 7) << 2;
            int gc = n0 + cb + cc;
            long long o = (long long)(m0 + row) * ldc + gc;
            float v[4];
            #pragma unroll
            for (int j = 0; j < 4; j++) {
                v[j] = stg[row * 33 + cc + j];
                if (EPI == 1 || EPI == 2 || EPI == 4) v[j] += bias[gc + j];
                if (EPI == 4) v[j] = 0.5f * v[j] * (1.0f + erff(v[j] * 0.70710678118654752f));
            }
            if (EPI <= 1) {
                *(float4*)(Cfp + o) = make_float4(v[0], v[1], v[2], v[3]);
            } else {
                bf16 h[4], l[4];
                #pragma unroll
                for (int j = 0; j < 4; j++) split2(v[j], h[j], l[j]);
                ((__nv_bfloat162*)(Chp + o))[0] = __nv_bfloat162(h[0], h[1]);
                ((__nv_bfloat162*)(Chp + o))[1] = __nv_bfloat162(h[2], h[3]);
                ((__nv_bfloat162*)(Clp + o))[0] = __nv_bfloat162(l[0], l[1]);
                ((__nv_bfloat162*)(Clp + o))[1] = __nv_bfloat162(l[2], l[3]);
            }
        }
        __syncthreads();
    }

    TCGEN05_FENCE_BEFORE();
    __syncthreads();
    if (tid == 0) { MBARRIER_INVAL(mb0); MBARRIER_INVAL(mb1); }
    if (wid == 4) TCGEN05_DEALLOC(tmem, 128);
#else
    // legacy epilogue: direct stores from register accumulators
    #pragma unroll
    for (int mt = 0; mt < 4; mt++)
        #pragma unroll
        for (int nt = 0; nt < 4; nt++)
            #pragma unroll
            for (int h2 = 0; h2 < 2; h2++) {
                int r = m0 + wm * 64 + mt * 16 + (lane >> 2) + h2 * 8;
                int c = n0 + wn * 32 + nt * 8 + ((lane & 3) << 1);
                if (c >= n0 + nB) continue;
                float v0 = acc[mt][nt][h2 * 2 + 0];
                float v1 = acc[mt][nt][h2 * 2 + 1];
                if (EPI == 1 || EPI == 2 || EPI == 4) { v0 += bias[c]; v1 += bias[c + 1]; }
                if (EPI == 4) {
                    v0 = 0.5f * v0 * (1.0f + erff(v0 * 0.70710678118654752f));
                    v1 = 0.5f * v1 * (1.0f + erff(v1 * 0.70710678118654752f));
                }
                long long o = (long long)r * ldc + c;
                if (EPI <= 1) {
                    Cfp[o] = v0; Cfp[o + 1] = v1;
                } else {
                    split2(v0, Chp[o], Clp[o]);
                    split2(v1, Chp[o + 1], Clp[o + 1]);
                }
            }
#endif
}

// ---------------- fp32 -> bf16 hi/lo split ----------------
__global__ void conv_pair(const float4* __restrict__ src, bf16* __restrict__ h,
                          bf16* __restrict__ l, int n4)
{
    int i = blockIdx.x * 256 + threadIdx.x;
    if (i < n4) {
        float4 v = src[i];
        int b = i * 4;
        split2(v.x, h[b], l[b]);
        split2(v.y, h[b + 1], l[b + 1]);
        split2(v.z, h[b + 2], l[b + 2]);
        split2(v.w, h[b + 3], l[b + 3]);
    }
}

// ---------------- transpose + split ----------------
__global__ void transpose_split(const float* __restrict__ src, long long sSb, long long sSh, int Hdiv,
                                bf16* __restrict__ dh, bf16* __restrict__ dl, long long sD,
                                int R, int C, int lds, int ldd)
{
    __shared__ float t[32][33];
    int zb = blockIdx.z / Hdiv, zh = blockIdx.z % Hdiv;
    const float* s = src + zb * sSb + zh * sSh;
    bf16* oh = dh + (long long)blockIdx.z * sD;
    bf16* ol = dl + (long long)blockIdx.z * sD;
    int r0 = blockIdx.y * 32, c0 = blockIdx.x * 32;
    int tx = threadIdx.x, ty = threadIdx.y;
    #pragma unroll
    for (int i = 0; i < 4; i++) {
        int r = r0 + ty + i * 8;
        if (r < R && c0 + tx < C) t[ty + i * 8][tx] = s[(long long)r * lds + c0 + tx];
    }
    __syncthreads();
    #pragma unroll
    for (int i = 0; i < 4; i++) {
        int c = c0 + ty + i * 8, r = r0 + tx;
        if (c < C && r < R) {
            long long o = (long long)c * ldd + r;
            split2(t[tx][ty + i * 8], oh[o], ol[o]);
        }
    }
}

// ---------------- diag -> 1/||c|| ----------------
__global__ void diag_rsqrt_kernel(const float* __restrict__ Gc, float* __restrict__ cninv)
{
    int i = blockIdx.x * 256 + threadIdx.x;
    if (i < NBH * NS) {
        int bh = i / NS, s = i % NS;
        cninv[i] = rsqrtf(Gc[((long long)bh * NS + s) * NS + s]);
    }
}

// ---------------- block reduce ----------------
__device__ __forceinline__ float block_reduce(float v, bool ismax, float* red)
{
    int lane = threadIdx.x & 31, w = threadIdx.x >> 5;
    #pragma unroll
    for (int o = 16; o; o >>= 1) {
        float u = __shfl_xor_sync(0xffffffffu, v, o);
        v = ismax ? fmaxf(v, u) : (v + u);
    }
    if (lane == 0) red[w] = v;
    __syncthreads();
    float r = red[0];
    #pragma unroll
    for (int i = 1; i < 8; i++) r = ismax ? fmaxf(r, red[i]) : (r + red[i]);
    __syncthreads();
    return r;
}

// ---------------- blend + dual softmax -> P (bf16 hi/lo) ----------------
__global__ __launch_bounds__(256) void blend_softmax_kernel(
    const float* __restrict__ Gc, const float* __restrict__ Gqk,
    const float* __restrict__ cninv, bf16* __restrict__ ph, bf16* __restrict__ pl)
{
    int l = blockIdx.x;
    int bh = blockIdx.y;
    long long base = ((long long)bh * NS + l) * NS;
    const float* gc = Gc + base;
    const float* gq = Gqk + base;
    const float* cn = cninv + bh * NS;
    int t = threadIdx.x;

    __shared__ float red[8];
    float cl = cn[l];

    float s1[2], s2[2];
    #pragma unroll
    for (int j = 0; j < 2; j++) {
        int r = t + j * 256;
        s1[j] = 1.0f - gc[r] * cl * cn[r] + (r == l ? 1.0f : 0.0f);
        s2[j] = gq[r] * 0.125f;
    }
    float m1 = block_reduce(fmaxf(s1[0], s1[1]), true, red);
    float m2 = block_reduce(fmaxf(s2[0], s2[1]), true, red);
    float e1[2], e2[2];
    #pragma unroll
    for (int j = 0; j < 2; j++) { e1[j] = expf(s1[j] - m1); e2[j] = expf(s2[j] - m2); }
    float sum1 = block_reduce(e1[0] + e1[1], false, red);
    float sum2 = block_reduce(e2[0] + e2[1], false, red);
    float inv1 = 0.5f / sum1, inv2 = 0.5f / sum2;
    #pragma unroll
    for (int j = 0; j < 2; j++) {
        int r = t + j * 256;
        split2(e1[j] * inv1 + e2[j] * inv2, ph[base + r], pl[base + r]);
    }
}

// ---------------- residual add + LayerNorm ----------------
__global__ __launch_bounds__(256) void add_ln_kernel(
    const float* __restrict__ inp, const float* __restrict__ res,
    const float* __restrict__ g, const float* __restrict__ b,
    float* __restrict__ outf, bf16* __restrict__ outh, bf16* __restrict__ outl)
{
    long long row = blockIdx.x;
    const float* ip = inp + row * ND;
    const float* rp = res + row * ND;
    int t = threadIdx.x;

    __shared__ float buf[ND];
    __shared__ float red[8];

    float s = 0.f;
    for (int c = t; c < ND; c += 256) {
        float v = ip[c] + rp[c];
        buf[c] = v;
        s += v;
    }
    s = block_reduce(s, false, red);
    float mu = s * (1.0f / ND);
    float vs = 0.f;
    for (int c = t; c < ND; c += 256) {
        float d = buf[c] - mu;
        vs += d * d;
    }
    vs = block_reduce(vs, false, red);
    float inv = rsqrtf(vs * (1.0f / ND) + 1e-12f);
    for (int c = t; c < ND; c += 256) {
        float v = (buf[c] - mu) * inv * g[c] + b[c];
        long long o = row * ND + c;
        outf[o] = v;
        split2(v, outh[o], outl[o]);
    }
}

// ---------------- host ----------------
static float* symf(const void* s) { void* p = nullptr; cudaGetSymbolAddress(&p, s); return (float*)p; }
static bf16*  symb(const void* s) { void* p = nullptr; cudaGetSymbolAddress(&p, s); return (bf16*)p; }

extern "C" void kernel_launch(void* const* d_in, const int* in_sizes, int n_in,
                              void* d_out, int out_size)
{
    const float* hs  = (const float*)d_in[0];
    const float* Wq  = (const float*)d_in[1];  const float* bq  = (const float*)d_in[2];
    const float* Wk  = (const float*)d_in[3];  const float* bk  = (const float*)d_in[4];
    const float* Wv  = (const float*)d_in[5];  const float* bv  = (const float*)d_in[6];
    const float* Wc  = (const float*)d_in[7];  const float* bc  = (const float*)d_in[8];
    const float* Wo  = (const float*)d_in[9];  const float* bo  = (const float*)d_in[10];
    const float* g1  = (const float*)d_in[11]; const float* b1  = (const float*)d_in[12];
    const float* Wi  = (const float*)d_in[13]; const float* bi  = (const float*)d_in[14];
    const float* Wo2 = (const float*)d_in[15]; const float* bo2 = (const float*)d_in[16];
    const float* g2  = (const float*)d_in[17]; const float* b2  = (const float*)d_in[18];

    cudaFuncSetAttribute(gemm_tc<0>, cudaFuncAttributeMaxDynamicSharedMemorySize, GSM);
    cudaFuncSetAttribute(gemm_tc<1>, cudaFuncAttributeMaxDynamicSharedMemorySize, GSM);
    cudaFuncSetAttribute(gemm_tc<2>, cudaFuncAttributeMaxDynamicSharedMemorySize, GSM);
    cudaFuncSetAttribute(gemm_tc<3>, cudaFuncAttributeMaxDynamicSharedMemorySize, GSM);
    cudaFuncSetAttribute(gemm_tc<4>, cudaFuncAttributeMaxDynamicSharedMemorySize, GSM);

    float* XF   = symf(g_xf);
    float* VF   = symf(g_vf);
    float* TMP  = symf(g_tmp);
    float* ATTF = symf(g_attnf);
    float* S1   = symf(g_s1);
    float* S2   = symf(g_s2);
    float* CN   = symf(g_cninv);

    bf16 *XH = symb(g_xh), *XL = symb(g_xl);
    bf16 *QH = symb(g_qh), *QL = symb(g_ql);
    bf16 *KH = symb(g_kh), *KL = symb(g_kl);
    bf16 *CH = symb(g_ch), *CL = symb(g_cl);
    bf16 *CXH = symb(g_ctxh), *CXL = symb(g_ctxl);
    bf16 *ATH = symb(g_ath), *ATL = symb(g_atl);
    bf16 *HH = symb(g_hh), *HL = symb(g_hl);
    bf16 *PH = symb(g_ph), *PL = symb(g_pl);
    bf16 *VTH = symb(g_vth), *VTL = symb(g_vtl);

    bf16 *WQH = symb(g_wqh), *WQL = symb(g_wql);
    bf16 *WKH = symb(g_wkh), *WKL = symb(g_wkl);
    bf16 *WVH = symb(g_wvh), *WVL = symb(g_wvl);
    bf16 *WCH = symb(g_wch), *WCL = symb(g_wcl);
    bf16 *WOH = symb(g_woh), *WOL = symb(g_wol);
    bf16 *WIH = symb(g_wih), *WIL = symb(g_wil);
    bf16 *WO2H = symb(g_wo2h), *WO2L = symb(g_wo2l);

    const long long SD  = (long long)NS * ND;
    const long long SS  = (long long)NS * NS;
    const long long HSS = (long long)NH * SS;
    const long long VTS = (long long)NDH * NS;

    const uint32_t ID128 = 0x8000490u | (16u << 17);   // M=128, N=128, bf16, f32 acc
    const uint32_t ID64  = 0x8000490u | (8u << 17);    // M=128, N=64

    dim3 tb(32, 8);
    transpose_split<<<dim3(24, 24, NL), tb>>>(Wq,  WDD, 0, 1, WQH,  WQL,  WDD, 768, 768, 768, 768);
    transpose_split<<<dim3(24, 24, NL), tb>>>(Wk,  WDD, 0, 1, WKH,  WKL,  WDD, 768, 768, 768, 768);
    transpose_split<<<dim3(24, 24, NL), tb>>>(Wv,  WDD, 0, 1, WVH,  WVL,  WDD, 768, 768, 768, 768);
    transpose_split<<<dim3(24, 24, NL), tb>>>(Wc,  WDD, 0, 1, WCH,  WCL,  WDD, 768, 768, 768, 768);
    transpose_split<<<dim3(24, 24, NL), tb>>>(Wo,  WDD, 0, 1, WOH,  WOL,  WDD, 768, 768, 768, 768);
    transpose_split<<<dim3(96, 24, NL), tb>>>(Wi,  WDF, 0, 1, WIH,  WIL,  WDF, 768, 3072, 3072, 768);
    transpose_split<<<dim3(24, 96, NL), tb>>>(Wo2, WDF, 0, 1, WO2H, WO2L, WDF, 3072, 768, 768, 3072);

    cudaMemcpyAsync(XF, hs, sizeof(float) * MROWS * ND, cudaMemcpyDeviceToDevice);
    conv_pair<<<(MROWS * ND / 4 + 255) / 256, 256>>>((const float4*)hs, XH, XL, MROWS * ND / 4);

    for (int i = 0; i < NL; i++) {
        const size_t oDD = (size_t)i * WDD, oDF = (size_t)i * WDF;

        dim3 gP(6, 64, 1);
        gemm_tc<2><<<gP, 256, GSM>>>(XH, XL, 768, 0, 0, WQH + oDD, WQL + oDD, 768, 0, 0,
            nullptr, QH, QL, 768, 0, 0, bq + i * ND, 768, 768, 1, ID128);
        gemm_tc<2><<<gP, 256, GSM>>>(XH, XL, 768, 0, 0, WKH + oDD, WKL + oDD, 768, 0, 0,
            nullptr, KH, KL, 768, 0, 0, bk + i * ND, 768, 768, 1, ID128);
        gemm_tc<2><<<gP, 256, GSM>>>(XH, XL, 768, 0, 0, WCH + oDD, WCL + oDD, 768, 0, 0,
            nullptr, CH, CL, 768, 0, 0, bc + i * ND, 768, 768, 1, ID128);
        gemm_tc<1><<<gP, 256, GSM>>>(XH, XL, 768, 0, 0, WVH + oDD, WVL + oDD, 768, 0, 0,
            VF, nullptr, nullptr, 768, 0, 0, bv + i * ND, 768, 768, 1, ID128);

        transpose_split<<<dim3(2, 16, NBH), tb>>>(VF, SD, NDH, NH, VTH, VTL, VTS, 512, 64, 768, 512);

        dim3 gS(4, 4, NBH);
        gemm_tc<0><<<gS, 256, GSM>>>(CH, CL, 768, SD, NDH, CH, CL, 768, SD, NDH,
            S1, nullptr, nullptr, 512, HSS, SS, nullptr, 512, 64, NH, ID128);
        gemm_tc<0><<<gS, 256, GSM>>>(QH, QL, 768, SD, NDH, KH, KL, 768, SD, NDH,
            S2, nullptr, nullptr, 512, HSS, SS, nullptr, 512, 64, NH, ID128);

        diag_rsqrt_kernel<<<(NBH * NS + 255) / 256, 256>>>(S1, CN);
        blend_softmax_kernel<<<dim3(NS, NBH), 256>>>(S1, S2, CN, PH, PL);

        dim3 gC(1, 4, NBH);
        gemm_tc<3><<<gC, 256, GSM>>>(PH, PL, 512, HSS, SS, VTH, VTL, 512, (long long)NH * VTS, VTS,
            nullptr, CXH, CXL, 768, SD, NDH, nullptr, 64, 512, NH, ID64);

        gemm_tc<1><<<gP, 256, GSM>>>(CXH, CXL, 768, 0, 0, WOH + oDD, WOL + oDD, 768, 0, 0,
            TMP, nullptr, nullptr, 768, 0, 0, bo + i * ND, 768, 768, 1, ID128);
        add_ln_kernel<<<MROWS, 256>>>(TMP, XF, g1 + i * ND, b1 + i * ND, ATTF, ATH, ATL);

        dim3 gI(24, 64, 1);
        gemm_tc<4><<<gI, 256, GSM>>>(ATH, ATL, 768, 0, 0, WIH + oDF, WIL + oDF, 768, 0, 0,
            nullptr, HH, HL, 3072, 0, 0, bi + i * NF, 3072, 768, 1, ID128);

        gemm_tc<1><<<gP, 256, GSM>>>(HH, HL, 3072, 0, 0, WO2H + oDF, WO2L + oDF, 3072, 0, 0,
            TMP, nullptr, nullptr, 768, 0, 0, bo2 + i * ND, 768, 3072, 1, ID128);
        add_ln_kernel<<<MROWS, 256>>>(TMP, ATTF, g2 + i * ND, b2 + i * ND, XF, XH, XL);
    }

    cudaMemcpyAsync(d_out, XF, sizeof(float) * MROWS * ND, cudaMemcpyDeviceToDevice);
}

// round 5
// speedup vs baseline: 4.8913x; 1.1177x over previous
#include <cuda_runtime.h>
#include <cuda_bf16.h>
#include <math.h>
#include <stdint.h>

#define NH 12
#define NB 16
#define NS 512
#define ND 768
#define NF 3072
#define NL 4
#define NDH 64
#define MROWS (NB*NS)      // 8192
#define NBH (NB*NH)        // 192

typedef __nv_bfloat16 bf16;

#if defined(__CUDA_ARCH_FEAT_SM103_ALL)
#define HAS_TC 1
#else
#define HAS_TC 0
#endif

// ---------------- scratch ----------------
__device__ float g_xf[MROWS*ND];
__device__ float g_tmp[MROWS*ND];
__device__ float g_attnf[MROWS*ND];
__device__ float g_s1[(size_t)NBH*NS*NS];
__device__ float g_s2[(size_t)NBH*NS*NS];
__device__ float g_cninv[NBH*NS];

__device__ bf16 g_xh[MROWS*ND],   g_xl[MROWS*ND];
__device__ bf16 g_prjh[(size_t)MROWS*4*ND], g_prjl[(size_t)MROWS*4*ND]; // [8192, 3072] q|k|c|v
__device__ bf16 g_ctxh[MROWS*ND], g_ctxl[MROWS*ND];
__device__ bf16 g_ath[MROWS*ND],  g_atl[MROWS*ND];
__device__ bf16 g_hh[(size_t)MROWS*NF], g_hl[(size_t)MROWS*NF];
__device__ bf16 g_ph[(size_t)NBH*NS*NS], g_pl[(size_t)NBH*NS*NS];
__device__ bf16 g_vth[NBH*NDH*NS], g_vtl[NBH*NDH*NS];

#define WDD (768*768)
#define WDF (768*3072)
#define CATW (4*WDD)                     // per-layer fused-weight stride
__device__ bf16 g_wcath[NL*CATW], g_wcatl[NL*CATW];   // [3072,768] per layer (qT|kT|cT|vT)
__device__ bf16 g_woh[NL*WDD], g_wol[NL*WDD];
__device__ bf16 g_wih[NL*WDF], g_wil[NL*WDF];
__device__ bf16 g_wo2h[NL*WDF], g_wo2l[NL*WDF];
__device__ float g_bcat[NL*4*ND];

// ---------------- helpers ----------------
__device__ __forceinline__ void split2(float v, bf16& h, bf16& l) {
    h = __float2bfloat16(v);
    l = __float2bfloat16(v - __bfloat162float(h));
}

__device__ __forceinline__ void cpa16(uint32_t dst, const void* src, int sz) {
    asm volatile("cp.async.cg.shared.global [%0], [%1], 16, %2;" :: "r"(dst), "l"(src), "r"(sz));
}

#define FENCE_PROXY_ASYNC() \
    asm volatile("fence.proxy.async.shared::cta;" ::: "memory")

#if HAS_TC
__device__ __forceinline__ uint32_t elect_one_pred() {
    uint32_t pred;
    asm volatile(
        "{\n\t.reg .pred p;\n\t"
        "elect.sync _|p, 0xFFFFFFFF;\n\t"
        "selp.b32 %0, 1, 0, p;\n\t}"
        : "=r"(pred));
    return pred;
}

static constexpr uint64_t SMEM_DESC_BASE_SW128 =
    (uint64_t(2) << 61) | (uint64_t(1) << 46) | (uint64_t(64) << 32) | (uint64_t(1) << 16);
#define MAKE_SMEM_DESC(base_addr) \
    (SMEM_DESC_BASE_SW128 | ((uint64_t)((base_addr) >> 4) & 0x3FFF))

#define TCGEN05_ALLOC(smem_result_addr, nCols) \
    asm volatile("tcgen05.alloc.cta_group::1.sync.aligned.shared::cta.b32 [%0], %1;" \
        :: "r"((uint32_t)(smem_result_addr)), "r"((uint32_t)(nCols)) : "memory")
#define TCGEN05_DEALLOC(tmem_addr, nCols) \
    asm volatile("tcgen05.dealloc.cta_group::1.sync.aligned.b32 %0, %1;" \
        :: "r"(tmem_addr), "r"((uint32_t)(nCols)))
#define TCGEN05_RELINQ() \
    asm volatile("tcgen05.relinquish_alloc_permit.cta_group::1.sync.aligned;")
#define TCGEN05_COMMIT(mbar) \
    asm volatile("tcgen05.commit.cta_group::1.mbarrier::arrive::one.shared::cluster.b64 [%0];" \
        :: "r"((uint32_t)(mbar)) : "memory")
#define TCGEN05_WAIT_LD() \
    asm volatile("tcgen05.wait::ld.sync.aligned;" ::: "memory")
#define TCGEN05_FENCE_AFTER() \
    asm volatile("tcgen05.fence::after_thread_sync;" ::: "memory")
#define TCGEN05_FENCE_BEFORE() \
    asm volatile("tcgen05.fence::before_thread_sync;" ::: "memory")

#define MBARRIER_INIT(mbar, count) \
    asm volatile("mbarrier.init.shared.b64 [%0], %1;" \
        :: "r"((uint32_t)(mbar)), "r"((uint32_t)(count)) : "memory")
#define MBARRIER_INVAL(mbar) \
    asm volatile("mbarrier.inval.shared.b64 [%0];" :: "r"((uint32_t)(mbar)) : "memory")
#define MBARRIER_WAIT_PARITY(mbar_addr, phase_parity) do { \
    uint32_t _mbar = (uint32_t)(mbar_addr); \
    uint32_t _parity = (uint32_t)(phase_parity); \
    uint32_t _done; \
    asm volatile( \
        "{\n\t.reg .pred p;\n\t" \
        "mbarrier.try_wait.parity.acquire.cta.shared::cta.b64 p, [%1], %2;\n\t" \
        "selp.b32 %0, 1, 0, p;\n\t}" \
        : "=r"(_done) : "r"(_mbar), "r"(_parity) : "memory"); \
    if (!_done) { \
        asm volatile( \
            "{\n\t.reg .pred P1;\n\t" \
            "WAIT_LOOP_%=:\n\t" \
            "mbarrier.try_wait.parity.acquire.cta.shared::cta.b64 P1, [%0], %1, 0x989680;\n\t" \
            "@P1 bra.uni WAIT_DONE_%=;\n\t" \
            "bra.uni WAIT_LOOP_%=;\n\t" \
            "WAIT_DONE_%=:\n\t}" \
            :: "r"(_mbar), "r"(_parity) : "memory"); \
    } \
} while(0)

#define TCGEN05_LD_32X32B_X32(r, tmem_addr) \
    asm volatile( \
        "tcgen05.ld.sync.aligned.32x32b.x32.b32 " \
        "{%0, %1, %2, %3, %4, %5, %6, %7, " \
        " %8, %9, %10, %11, %12, %13, %14, %15, " \
        " %16, %17, %18, %19, %20, %21, %22, %23, " \
        " %24, %25, %26, %27, %28, %29, %30, %31}, [%32];" \
        : "=r"((r)[0]),  "=r"((r)[1]),  "=r"((r)[2]),  "=r"((r)[3]), \
          "=r"((r)[4]),  "=r"((r)[5]),  "=r"((r)[6]),  "=r"((r)[7]), \
          "=r"((r)[8]),  "=r"((r)[9]),  "=r"((r)[10]), "=r"((r)[11]), \
          "=r"((r)[12]), "=r"((r)[13]), "=r"((r)[14]), "=r"((r)[15]), \
          "=r"((r)[16]), "=r"((r)[17]), "=r"((r)[18]), "=r"((r)[19]), \
          "=r"((r)[20]), "=r"((r)[21]), "=r"((r)[22]), "=r"((r)[23]), \
          "=r"((r)[24]), "=r"((r)[25]), "=r"((r)[26]), "=r"((r)[27]), \
          "=r"((r)[28]), "=r"((r)[29]), "=r"((r)[30]), "=r"((r)[31]) \
        : "r"(tmem_addr))

__device__ __forceinline__ void mma_f16_ss(uint32_t d, uint64_t ad, uint64_t bd,
                                           uint32_t idesc, uint32_t en) {
    asm volatile(
        "{\n\t.reg .pred p;\n\t"
        "setp.ne.u32 p, %5, 0;\n\t"
        "tcgen05.mma.cta_group::1.kind::f16 [%0], %1, %2, %3, {%4, %4, %4, %4}, p;\n\t}"
        :: "r"(d), "l"(ad), "l"(bd), "r"(idesc), "r"(0u), "r"(en) : "memory");
}
#endif

// ---------------- bf16x3 NT GEMM, TN-templated tile (128 x TN) ----------------
// C[m,n] = sum_k (Ahi+Alo)[m,k]*(Bhi+Blo)[n,k]
// EPI: 0 f32, 1 f32+bias, 2 pair+bias, 3 pair, 4 pair+bias+gelu
// stages: 1 if K<=64 else 2 (host passes matching dynamic smem size)
template<int EPI, int TN>
__global__ void __launch_bounds__(256) gemm_tc(
    const bf16* __restrict__ Ah_, const bf16* __restrict__ Al_,
    int lda, long long sAb, long long sAh,
    const bf16* __restrict__ Bh_, const bf16* __restrict__ Bl_,
    int ldb, long long sBb, long long sBh,
    float* __restrict__ Cf, bf16* __restrict__ Coh, bf16* __restrict__ Col,
    int ldc, long long sCb, long long sCh,
    const float* __restrict__ bias,
    int N, int K, int Hdiv, uint32_t idesc)
{
    constexpr int STAGE = (128 + TN) * 256;
    constexpr int AHOF = 0, ALOF = 16384, BHOF = 32768, BLOF = 32768 + TN * 128;
    extern __shared__ __align__(1024) char dsm[];
    const int tid = threadIdx.x, lane = tid & 31, wid = tid >> 5;
    const int zb = blockIdx.z / Hdiv, zh = blockIdx.z % Hdiv;
    const int m0 = blockIdx.y * 128, n0 = blockIdx.x * TN;
    const int nB = min(TN, N - n0);

    const bf16* Agh = Ah_ + zb*sAb + zh*sAh + (long long)m0 * lda;
    const bf16* Agl = Al_ + zb*sAb + zh*sAh + (long long)m0 * lda;
    const bf16* Bgh = Bh_ + zb*sBb + zh*sBh + (long long)n0 * ldb;
    const bf16* Bgl = Bl_ + zb*sBb + zh*sBh + (long long)n0 * ldb;

    float* Cfp = Cf  ? Cf  + zb*sCb + zh*sCh : nullptr;
    bf16*  Chp = Coh ? Coh + zb*sCb + zh*sCh : nullptr;
    bf16*  Clp = Col ? Col + zb*sCb + zh*sCh : nullptr;

#if HAS_TC
    const int nst = (K > 64) ? 2 : 1;
    uint32_t sb  = (uint32_t)__cvta_generic_to_shared(dsm);
    uint32_t ctl = sb + (uint32_t)(nst * STAGE);
    uint32_t mb0 = ctl + 8, mb1 = ctl + 16;

    if (tid == 0) { MBARRIER_INIT(mb0, 1); MBARRIER_INIT(mb1, 1); }
    if (wid == 4) { TCGEN05_ALLOC(ctl, TN); TCGEN05_RELINQ(); }
    __syncthreads();
    uint32_t tmem;
    asm volatile("ld.shared.b32 %0, [%1];" : "=r"(tmem) : "r"(ctl));

    const int KT = K >> 6;
    int ph0 = 0, ph1 = 0;

    auto issue = [&](int buf, int k0) {
        const uint32_t sbase = sb + (uint32_t)(buf * STAGE);
        constexpr int ITER = (128 + TN) * 8 / 256;
        #pragma unroll
        for (int i = 0; i < ITER; i++) {
            int id = tid + (i << 8);
            int row = id >> 3, cc = id & 7;
            if (row < 128) {
                uint32_t off = (uint32_t)((row << 7) + (cc << 4));
                uint32_t sw = off ^ ((off >> 3) & 0x70);
                long long ga = (long long)row * lda + k0 + (cc << 3);
                cpa16(sbase + AHOF + sw, Agh + ga, 16);
                cpa16(sbase + ALOF + sw, Agl + ga, 16);
            } else {
                int rb = row - 128;
                uint32_t off = (uint32_t)((rb << 7) + (cc << 4));
                uint32_t sw = off ^ ((off >> 3) & 0x70);
                int sz = 16, br = rb;
                if (rb >= nB) { sz = 0; br = 0; }
                long long gb = (long long)br * ldb + k0 + (cc << 3);
                cpa16(sbase + BHOF + sw, Bgh + gb, sz);
                cpa16(sbase + BLOF + sw, Bgl + gb, sz);
            }
        }
        asm volatile("cp.async.commit_group;");
    };

    issue(0, 0);
    for (int kt = 0; kt < KT; kt++) {
        const int buf = (nst == 2) ? (kt & 1) : 0;
        if (kt + 1 < KT) {
            if (kt >= 1) {
                if ((buf ^ 1) == 0) { MBARRIER_WAIT_PARITY(mb0, ph0); ph0 ^= 1; }
                else                { MBARRIER_WAIT_PARITY(mb1, ph1); ph1 ^= 1; }
            }
            issue(buf ^ 1, (kt + 1) << 6);
            asm volatile("cp.async.wait_group 1;");
        } else {
            asm volatile("cp.async.wait_group 0;");
        }
        FENCE_PROXY_ASYNC();
        __syncthreads();

        const uint32_t sbase = sb + (uint32_t)(buf * STAGE);
        if (wid == 4) {
            if (elect_one_pred()) {
                uint64_t dah = MAKE_SMEM_DESC(sbase + AHOF);
                uint64_t dal = MAKE_SMEM_DESC(sbase + ALOF);
                uint64_t dbh = MAKE_SMEM_DESC(sbase + BHOF);
                uint64_t dbl = MAKE_SMEM_DESC(sbase + BLOF);
                #pragma unroll
                for (int s = 0; s < 4; s++) {
                    uint32_t en0 = (kt == 0 && s == 0) ? 0u : 1u;
                    mma_f16_ss(tmem, dah + s*2, dbh + s*2, idesc, en0);
                    mma_f16_ss(tmem, dah + s*2, dbl + s*2, idesc, 1u);
                    mma_f16_ss(tmem, dal + s*2, dbh + s*2, idesc, 1u);
                }
                TCGEN05_COMMIT(buf ? mb1 : mb0);
            }
        }
        __syncthreads();
    }

    const int lastbuf = (nst == 2) ? ((KT - 1) & 1) : 0;
    if (lastbuf == 0) { MBARRIER_WAIT_PARITY(mb0, ph0); }
    else              { MBARRIER_WAIT_PARITY(mb1, ph1); }
    TCGEN05_FENCE_AFTER();

    float* stg = (float*)dsm;
    for (int cb = 0; cb < nB; cb += 32) {
        if (wid < 4) {
            uint32_t d[32];
            TCGEN05_LD_32X32B_X32(d, tmem + cb);
            TCGEN05_WAIT_LD();
            int row = (wid << 5) + lane;
            #pragma unroll
            for (int j = 0; j < 32; j++) stg[row * 33 + j] = __uint_as_float(d[j]);
        }
        __syncthreads();
        #pragma unroll
        for (int it = 0; it < 4; it++) {
            int row = (it << 5) + (tid >> 3);
            int cc = (tid & 7) << 2;
            int gc = n0 + cb + cc;
            long long o = (long long)(m0 + row) * ldc + gc;
            float v[4];
            #pragma unroll
            for (int j = 0; j < 4; j++) {
                v[j] = stg[row * 33 + cc + j];
                if (EPI == 1 || EPI == 2 || EPI == 4) v[j] += bias[gc + j];
                if (EPI == 4) v[j] = 0.5f * v[j] * (1.0f + erff(v[j] * 0.70710678118654752f));
            }
            if (EPI <= 1) {
                *(float4*)(Cfp + o) = make_float4(v[0], v[1], v[2], v[3]);
            } else {
                bf16 h[4], l[4];
                #pragma unroll
                for (int j = 0; j < 4; j++) split2(v[j], h[j], l[j]);
                ((__nv_bfloat162*)(Chp + o))[0] = __nv_bfloat162(h[0], h[1]);
                ((__nv_bfloat162*)(Chp + o))[1] = __nv_bfloat162(h[2], h[3]);
                ((__nv_bfloat162*)(Clp + o))[0] = __nv_bfloat162(l[0], l[1]);
                ((__nv_bfloat162*)(Clp + o))[1] = __nv_bfloat162(l[2], l[3]);
            }
        }
        __syncthreads();
    }

    TCGEN05_FENCE_BEFORE();
    __syncthreads();
    if (tid == 0) { MBARRIER_INVAL(mb0); MBARRIER_INVAL(mb1); }
    if (wid == 4) TCGEN05_DEALLOC(tmem, TN);
#else
    // trivially-correct scalar fallback (never selected on sm_103a hardware)
    for (int o = tid; o < 128 * TN; o += 256) {
        int m = o / TN, n = o % TN;
        if (n >= nB) continue;
        float s = 0.f;
        const bf16* arh = Agh + (long long)m * lda;
        const bf16* arl = Agl + (long long)m * lda;
        const bf16* brh = Bgh + (long long)n * ldb;
        const bf16* brl = Bgl + (long long)n * ldb;
        for (int k = 0; k < K; k++)
            s += (__bfloat162float(arh[k]) + __bfloat162float(arl[k])) *
                 (__bfloat162float(brh[k]) + __bfloat162float(brl[k]));
        int gc = n0 + n;
        if (EPI == 1 || EPI == 2 || EPI == 4) s += bias[gc];
        if (EPI == 4) s = 0.5f * s * (1.0f + erff(s * 0.70710678118654752f));
        long long off = (long long)(m0 + m) * ldc + gc;
        if (EPI <= 1) Cfp[off] = s;
        else split2(s, Chp[off], Clp[off]);
    }
#endif
}

// ---------------- fp32 -> bf16 hi/lo split ----------------
__global__ void conv_pair(const float4* __restrict__ src, bf16* __restrict__ h,
                          bf16* __restrict__ l, int n4)
{
    int i = blockIdx.x * 256 + threadIdx.x;
    if (i < n4) {
        float4 v = src[i];
        int b = i * 4;
        split2(v.x, h[b], l[b]);
        split2(v.y, h[b + 1], l[b + 1]);
        split2(v.z, h[b + 2], l[b + 2]);
        split2(v.w, h[b + 3], l[b + 3]);
    }
}

// ---------------- transpose + split: fp32 [R,C] -> bf16 pair [C,R] ----------------
__global__ void transpose_split(const float* __restrict__ src, long long sS, 
                                bf16* __restrict__ dh, bf16* __restrict__ dl, long long sD,
                                int R, int C, int lds, int ldd)
{
    __shared__ float t[32][33];
    const float* s = src + (long long)blockIdx.z * sS;
    bf16* oh = dh + (long long)blockIdx.z * sD;
    bf16* ol = dl + (long long)blockIdx.z * sD;
    int r0 = blockIdx.y * 32, c0 = blockIdx.x * 32;
    int tx = threadIdx.x, ty = threadIdx.y;
    #pragma unroll
    for (int i = 0; i < 4; i++) {
        int r = r0 + ty + i * 8;
        if (r < R && c0 + tx < C) t[ty + i * 8][tx] = s[(long long)r * lds + c0 + tx];
    }
    __syncthreads();
    #pragma unroll
    for (int i = 0; i < 4; i++) {
        int c = c0 + ty + i * 8, r = r0 + tx;
        if (c < C && r < R) {
            long long o = (long long)c * ldd + r;
            split2(t[tx][ty + i * 8], oh[o], ol[o]);
        }
    }
}

// ---------------- pair transpose: bf16 pair [R,C] -> bf16 pair [C,R] ----------------
__global__ void transpose_pair(const bf16* __restrict__ sh, const bf16* __restrict__ sl,
                               long long sSb, long long sSh, int Hdiv,
                               bf16* __restrict__ dh, bf16* __restrict__ dl, long long sD,
                               int R, int C, int lds, int ldd)
{
    __shared__ uint32_t t[32][33];
    int zb = blockIdx.z / Hdiv, zh = blockIdx.z % Hdiv;
    long long so = zb * sSb + zh * sSh;
    bf16* oh = dh + (long long)blockIdx.z * sD;
    bf16* ol = dl + (long long)blockIdx.z * sD;
    int r0 = blockIdx.y * 32, c0 = blockIdx.x * 32;
    int tx = threadIdx.x, ty = threadIdx.y;
    #pragma unroll
    for (int i = 0; i < 4; i++) {
        int r = r0 + ty + i * 8;
        if (r < R && c0 + tx < C) {
            long long a = so + (long long)r * lds + c0 + tx;
            uint16_t hv = __bfloat16_as_ushort(sh[a]);
            uint16_t lv = __bfloat16_as_ushort(sl[a]);
            t[ty + i * 8][tx] = (uint32_t)hv | ((uint32_t)lv << 16);
        }
    }
    __syncthreads();
    #pragma unroll
    for (int i = 0; i < 4; i++) {
        int c = c0 + ty + i * 8, r = r0 + tx;
        if (c < C && r < R) {
            long long o = (long long)c * ldd + r;
            uint32_t v = t[tx][ty + i * 8];
            oh[o] = __ushort_as_bfloat16((uint16_t)(v & 0xffff));
            ol[o] = __ushort_as_bfloat16((uint16_t)(v >> 16));
        }
    }
}

// ---------------- diag -> 1/||c|| ----------------
__global__ void diag_rsqrt_kernel(const float* __restrict__ Gc, float* __restrict__ cninv)
{
    int i = blockIdx.x * 256 + threadIdx.x;
    if (i < NBH * NS) {
        int bh = i / NS, s = i % NS;
        cninv[i] = rsqrtf(Gc[((long long)bh * NS + s) * NS + s]);
    }
}

// ---------------- block reduce ----------------
__device__ __forceinline__ float block_reduce(float v, bool ismax, float* red)
{
    int lane = threadIdx.x & 31, w = threadIdx.x >> 5;
    #pragma unroll
    for (int o = 16; o; o >>= 1) {
        float u = __shfl_xor_sync(0xffffffffu, v, o);
        v = ismax ? fmaxf(v, u) : (v + u);
    }
    if (lane == 0) red[w] = v;
    __syncthreads();
    float r = red[0];
    #pragma unroll
    for (int i = 1; i < 8; i++) r = ismax ? fmaxf(r, red[i]) : (r + red[i]);
    __syncthreads();
    return r;
}

// ---------------- blend + dual softmax -> P pair ----------------
__global__ __launch_bounds__(256) void blend_softmax_kernel(
    const float* __restrict__ Gc, const float* __restrict__ Gqk,
    const float* __restrict__ cninv, bf16* __restrict__ ph, bf16* __restrict__ pl)
{
    int l = blockIdx.x;
    int bh = blockIdx.y;
    long long base = ((long long)bh * NS + l) * NS;
    const float* gc = Gc + base;
    const float* gq = Gqk + base;
    const float* cn = cninv + bh * NS;
    int t = threadIdx.x;

    __shared__ float red[8];
    float cl = cn[l];

    float s1[2], s2[2];
    #pragma unroll
    for (int j = 0; j < 2; j++) {
        int r = t + j * 256;
        s1[j] = 1.0f - gc[r] * cl * cn[r] + (r == l ? 1.0f : 0.0f);
        s2[j] = gq[r] * 0.125f;
    }
    float m1 = block_reduce(fmaxf(s1[0], s1[1]), true, red);
    float m2 = block_reduce(fmaxf(s2[0], s2[1]), true, red);
    float e1[2], e2[2];
    #pragma unroll
    for (int j = 0; j < 2; j++) { e1[j] = expf(s1[j] - m1); e2[j] = expf(s2[j] - m2); }
    float sum1 = block_reduce(e1[0] + e1[1], false, red);
    float sum2 = block_reduce(e2[0] + e2[1], false, red);
    float inv1 = 0.5f / sum1, inv2 = 0.5f / sum2;
    #pragma unroll
    for (int j = 0; j < 2; j++) {
        int r = t + j * 256;
        split2(e1[j] * inv1 + e2[j] * inv2, ph[base + r], pl[base + r]);
    }
}

// ---------------- residual add + LayerNorm ----------------
__global__ __launch_bounds__(256) void add_ln_kernel(
    const float* __restrict__ inp, const float* __restrict__ res,
    const float* __restrict__ g, const float* __restrict__ b,
    float* __restrict__ outf, bf16* __restrict__ outh, bf16* __restrict__ outl)
{
    long long row = blockIdx.x;
    const float* ip = inp + row * ND;
    const float* rp = res + row * ND;
    int t = threadIdx.x;

    __shared__ float buf[ND];
    __shared__ float red[8];

    float s = 0.f;
    for (int c = t; c < ND; c += 256) {
        float v = ip[c] + rp[c];
        buf[c] = v;
        s += v;
    }
    s = block_reduce(s, false, red);
    float mu = s * (1.0f / ND);
    float vs = 0.f;
    for (int c = t; c < ND; c += 256) {
        float d = buf[c] - mu;
        vs += d * d;
    }
    vs = block_reduce(vs, false, red);
    float inv = rsqrtf(vs * (1.0f / ND) + 1e-12f);
    for (int c = t; c < ND; c += 256) {
        float v = (buf[c] - mu) * inv * g[c] + b[c];
        long long o = row * ND + c;
        outf[o] = v;
        split2(v, outh[o], outl[o]);
    }
}

// ---------------- host ----------------
static float* symf(const void* s) { void* p = nullptr; cudaGetSymbolAddress(&p, s); return (float*)p; }
static bf16*  symb(const void* s) { void* p = nullptr; cudaGetSymbolAddress(&p, s); return (bf16*)p; }

#define SMEMSZ(TN, nst) ((nst) * ((128 + (TN)) * 256) + 64)

extern "C" void kernel_launch(void* const* d_in, const int* in_sizes, int n_in,
                              void* d_out, int out_size)
{
    const float* hs  = (const float*)d_in[0];
    const float* Wq  = (const float*)d_in[1];  const float* bq  = (const float*)d_in[2];
    const float* Wk  = (const float*)d_in[3];  const float* bk  = (const float*)d_in[4];
    const float* Wv  = (const float*)d_in[5];  const float* bv  = (const float*)d_in[6];
    const float* Wc  = (const float*)d_in[7];  const float* bc  = (const float*)d_in[8];
    const float* Wo  = (const float*)d_in[9];  const float* bo  = (const float*)d_in[10];
    const float* g1  = (const float*)d_in[11]; const float* b1  = (const float*)d_in[12];
    const float* Wi  = (const float*)d_in[13]; const float* bi  = (const float*)d_in[14];
    const float* Wo2 = (const float*)d_in[15]; const float* bo2 = (const float*)d_in[16];
    const float* g2  = (const float*)d_in[17]; const float* b2  = (const float*)d_in[18];

    const int SM256_2 = SMEMSZ(256, 2);   // 196672
    const int SM256_1 = SMEMSZ(256, 1);   // 98368
    const int SM64_2  = SMEMSZ(64, 2);    // 98368

    cudaFuncSetAttribute(gemm_tc<0, 256>, cudaFuncAttributeMaxDynamicSharedMemorySize, SM256_2);
    cudaFuncSetAttribute(gemm_tc<1, 256>, cudaFuncAttributeMaxDynamicSharedMemorySize, SM256_2);
    cudaFuncSetAttribute(gemm_tc<2, 256>, cudaFuncAttributeMaxDynamicSharedMemorySize, SM256_2);
    cudaFuncSetAttribute(gemm_tc<4, 256>, cudaFuncAttributeMaxDynamicSharedMemorySize, SM256_2);
    cudaFuncSetAttribute(gemm_tc<3, 64>,  cudaFuncAttributeMaxDynamicSharedMemorySize, SM64_2);

    float* XF   = symf(g_xf);
    float* TMP  = symf(g_tmp);
    float* ATTF = symf(g_attnf);
    float* S1   = symf(g_s1);
    float* S2   = symf(g_s2);
    float* CN   = symf(g_cninv);
    float* BCAT = symf(g_bcat);

    bf16 *XH = symb(g_xh), *XL = symb(g_xl);
    bf16 *PRJH = symb(g_prjh), *PRJL = symb(g_prjl);
    bf16 *CXH = symb(g_ctxh), *CXL = symb(g_ctxl);
    bf16 *ATH = symb(g_ath), *ATL = symb(g_atl);
    bf16 *HH = symb(g_hh), *HL = symb(g_hl);
    bf16 *PH = symb(g_ph), *PL = symb(g_pl);
    bf16 *VTH = symb(g_vth), *VTL = symb(g_vtl);

    bf16 *WCATH = symb(g_wcath), *WCATL = symb(g_wcatl);
    bf16 *WOH = symb(g_woh), *WOL = symb(g_wol);
    bf16 *WIH = symb(g_wih), *WIL = symb(g_wil);
    bf16 *WO2H = symb(g_wo2h), *WO2L = symb(g_wo2l);

    const long long SD   = (long long)NS * ND;       // x / ctx row-major batch stride
    const long long SDP  = (long long)NS * (4 * ND); // prj batch stride
    const long long SS   = (long long)NS * NS;
    const long long HSS  = (long long)NH * SS;
    const long long VTS  = (long long)NDH * NS;

    const uint32_t ID256 = 0x8000490u | (32u << 17);
    const uint32_t ID64  = 0x8000490u | (8u << 17);

    dim3 tb(32, 8);
    // fused projection weights: WCAT[layer] = [qT; kT; cT; vT]  (3072 x 768)
    transpose_split<<<dim3(24, 24, NL), tb>>>(Wq, WDD, WCATH + 0*WDD, WCATL + 0*WDD, CATW, 768, 768, 768, 768);
    transpose_split<<<dim3(24, 24, NL), tb>>>(Wk, WDD, WCATH + 1*WDD, WCATL + 1*WDD, CATW, 768, 768, 768, 768);
    transpose_split<<<dim3(24, 24, NL), tb>>>(Wc, WDD, WCATH + 2*WDD, WCATL + 2*WDD, CATW, 768, 768, 768, 768);
    transpose_split<<<dim3(24, 24, NL), tb>>>(Wv, WDD, WCATH + 3*WDD, WCATL + 3*WDD, CATW, 768, 768, 768, 768);
    transpose_split<<<dim3(24, 24, NL), tb>>>(Wo,  WDD, WOH,  WOL,  WDD, 768, 768, 768, 768);
    transpose_split<<<dim3(96, 24, NL), tb>>>(Wi,  WDF, WIH,  WIL,  WDF, 768, 3072, 3072, 768);
    transpose_split<<<dim3(24, 96, NL), tb>>>(Wo2, WDF, WO2H, WO2L, WDF, 3072, 768, 768, 3072);

    // concat bias
    for (int i = 0; i < NL; i++) {
        cudaMemcpyAsync(BCAT + i*4*ND + 0*ND, bq + i*ND, ND*4, cudaMemcpyDeviceToDevice);
        cudaMemcpyAsync(BCAT + i*4*ND + 1*ND, bk + i*ND, ND*4, cudaMemcpyDeviceToDevice);
        cudaMemcpyAsync(BCAT + i*4*ND + 2*ND, bc + i*ND, ND*4, cudaMemcpyDeviceToDevice);
        cudaMemcpyAsync(BCAT + i*4*ND + 3*ND, bv + i*ND, ND*4, cudaMemcpyDeviceToDevice);
    }

    cudaMemcpyAsync(XF, hs, sizeof(float) * MROWS * ND, cudaMemcpyDeviceToDevice);
    conv_pair<<<(MROWS * ND / 4 + 255) / 256, 256>>>((const float4*)hs, XH, XL, MROWS * ND / 4);

    for (int i = 0; i < NL; i++) {
        const size_t oDD = (size_t)i * WDD, oDF = (size_t)i * WDF, oCAT = (size_t)i * CATW;

        // fused q|k|c|v projection: [8192,768] @ [768,3072] -> PRJ pair
        gemm_tc<2, 256><<<dim3(12, 64, 1), 256, SM256_2>>>(
            XH, XL, 768, 0, 0, WCATH + oCAT, WCATL + oCAT, 768, 0, 0,
            nullptr, PRJH, PRJL, 3072, 0, 0, BCAT + i*4*ND, 3072, 768, 1, ID256);

        // V^T per head: PRJ cols [2304, 3072) -> VT pair [bh][64,512]
        transpose_pair<<<dim3(2, 16, NBH), tb>>>(PRJH + 3*ND, PRJL + 3*ND, SDP, NDH, NH,
                                                 VTH, VTL, VTS, 512, 64, 4*ND, 512);

        // score gram GEMMs (single K-chunk, 2 CTAs/SM)
        dim3 gS(2, 4, NBH);
        gemm_tc<0, 256><<<gS, 256, SM256_1>>>(
            PRJH + 2*ND, PRJL + 2*ND, 4*ND, SDP, NDH,
            PRJH + 2*ND, PRJL + 2*ND, 4*ND, SDP, NDH,
            S1, nullptr, nullptr, 512, HSS, SS, nullptr, 512, 64, NH, ID256);
        gemm_tc<0, 256><<<gS, 256, SM256_1>>>(
            PRJH + 0*ND, PRJL + 0*ND, 4*ND, SDP, NDH,
            PRJH + 1*ND, PRJL + 1*ND, 4*ND, SDP, NDH,
            S2, nullptr, nullptr, 512, HSS, SS, nullptr, 512, 64, NH, ID256);

        diag_rsqrt_kernel<<<(NBH * NS + 255) / 256, 256>>>(S1, CN);
        blend_softmax_kernel<<<dim3(NS, NBH), 256>>>(S1, S2, CN, PH, PL);

        // ctx = P @ V^T
        gemm_tc<3, 64><<<dim3(1, 4, NBH), 256, SM64_2>>>(
            PH, PL, 512, HSS, SS, VTH, VTL, 512, (long long)NH * VTS, VTS,
            nullptr, CXH, CXL, 768, SD, NDH, nullptr, 64, 512, NH, ID64);

        // attn_out = LN(ctx @ Wo + bo + x)
        gemm_tc<1, 256><<<dim3(3, 64, 1), 256, SM256_2>>>(
            CXH, CXL, 768, 0, 0, WOH + oDD, WOL + oDD, 768, 0, 0,
            TMP, nullptr, nullptr, 768, 0, 0, bo + i * ND, 768, 768, 1, ID256);
        add_ln_kernel<<<MROWS, 256>>>(TMP, XF, g1 + i * ND, b1 + i * ND, ATTF, ATH, ATL);

        // h = gelu(attn @ Wi + bi)
        gemm_tc<4, 256><<<dim3(12, 64, 1), 256, SM256_2>>>(
            ATH, ATL, 768, 0, 0, WIH + oDF, WIL + oDF, 768, 0, 0,
            nullptr, HH, HL, 3072, 0, 0, bi + i * NF, 3072, 768, 1, ID256);

        // x = LN(h @ Wo2 + bo2 + attn)
        gemm_tc<1, 256><<<dim3(3, 64, 1), 256, SM256_2>>>(
            HH, HL, 3072, 0, 0, WO2H + oDF, WO2L + oDF, 3072, 0, 0,
            TMP, nullptr, nullptr, 768, 0, 0, bo2 + i * ND, 768, 3072, 1, ID256);
        add_ln_kernel<<<MROWS, 256>>>(TMP, ATTF, g2 + i * ND, b2 + i * ND, XF, XH, XL);
    }

    cudaMemcpyAsync(d_out, XF, sizeof(float) * MROWS * ND, cudaMemcpyDeviceToDevice);
}